// round 14
// baseline (speedup 1.0000x reference)
#include <cuda_runtime.h>
#include <math.h>
#include <stdint.h>

#define NN 32768
#define NE 524288
#define HD 128
#define ASW 36

__device__ __forceinline__ float ssilu(float v) {
    return v / ((1.0f + __expf(-v)) * 0.6f);
}
__device__ __forceinline__ float f2tf32(float x) {
    float r;
    asm("cvt.rna.tf32.f32 %0, %1;" : "=f"(r) : "f"(x));
    return r;
}
__device__ __forceinline__ float4 rnd4(float4 v) {
    v.x = f2tf32(v.x); v.y = f2tf32(v.y);
    v.z = f2tf32(v.z); v.w = f2tf32(v.w);
    return v;
}

// scratch ------------------------------------------------------------------
static __device__ float g_xln[NN * HD];
static __device__ float g_t1[NN * HD];
static __device__ float g_xh[NN * 3 * HD];
static __device__ float g_dx[NN * HD];        // init = x, accumulates dx
static __device__ float g_dvec[NN * 3 * HD];  // init = vec, accumulates dvec
static __device__ float g_vproj[NN * 3 * 2 * HD];
static __device__ float g_vecdot[NN * HD];
static __device__ float g_cat[NN * 2 * HD];
static __device__ float g_u[NN * HD];
static __device__ float g_hbuf[NN * 3 * HD];
static __device__ float g_W1t[128 * 128];
static __device__ float g_W2t[128 * 384];
static __device__ float g_Wrt[64 * 384];
static __device__ float g_Wvt[128 * 256];
static __device__ float g_Wu1t[256 * 128];
static __device__ float g_Wu2t[128 * 384];

__constant__ float C_INV_SQRT_3 = 0.57735026918962576451f;
__constant__ float C_INV_SQRT_H = 0.08838834764831844055f;
__constant__ float C_INV_SQRT_2 = 0.70710678118654752440f;

// ---------------------------------------------------------------------------
__device__ __forceinline__ void cp16(float* s, const float* g) {
    uint32_t sa = (uint32_t)__cvta_generic_to_shared(s);
    asm volatile("cp.async.cg.shared.global [%0], [%1], 16;"
                 :: "r"(sa), "l"(g) : "memory");
}
__device__ __forceinline__ void mma8(float c[4], const uint32_t a[4],
                                     uint32_t b0, uint32_t b1) {
    asm volatile(
        "mma.sync.aligned.m16n8k8.row.col.f32.tf32.tf32.f32 "
        "{%0,%1,%2,%3}, {%4,%5,%6,%7}, {%8,%9}, {%0,%1,%2,%3};"
        : "+f"(c[0]), "+f"(c[1]), "+f"(c[2]), "+f"(c[3])
        : "r"(a[0]), "r"(a[1]), "r"(a[2]), "r"(a[3]), "r"(b0), "r"(b1));
}
__device__ __forceinline__ void red4(float* addr, float4 v) {
    asm volatile("red.global.add.v4.f32 [%0], {%1, %2, %3, %4};"
                 :: "l"(addr), "f"(v.x), "f"(v.y), "f"(v.z), "f"(v.w)
                 : "memory");
}

// ---------------------------------------------------------------------------
// prep_kernel: blocks [0,4096) LayerNorm; rest: dx=x, dvec=vec, weight round.
// ---------------------------------------------------------------------------
__global__ void prep_kernel(const float* __restrict__ x,
                            const float* __restrict__ vec,
                            const float* __restrict__ lng,
                            const float* __restrict__ lnb,
                            const float* __restrict__ W1,
                            const float* __restrict__ W2,
                            const float* __restrict__ Wr,
                            const float* __restrict__ Wv,
                            const float* __restrict__ Wu1,
                            const float* __restrict__ Wu2) {
    int blk = blockIdx.x;
    int tid = threadIdx.x;
    if (blk < 4096) {
        int row = blk * 8 + (tid >> 5);
        int lane = tid & 31;
        float4 v = *(const float4*)(x + (size_t)row * HD + lane * 4);
        float s = v.x + v.y + v.z + v.w;
        float s2 = v.x * v.x + v.y * v.y + v.z * v.z + v.w * v.w;
#pragma unroll
        for (int o = 16; o > 0; o >>= 1) {
            s += __shfl_xor_sync(0xffffffffu, s, o);
            s2 += __shfl_xor_sync(0xffffffffu, s2, o);
        }
        float mu = s * (1.0f / HD);
        float var = s2 * (1.0f / HD) - mu * mu;
        float inv = rsqrtf(var + 1e-5f);
        float4 gg = *(const float4*)(lng + lane * 4);
        float4 bb = *(const float4*)(lnb + lane * 4);
        float4 o4;
        o4.x = f2tf32((v.x - mu) * inv * gg.x + bb.x);
        o4.y = f2tf32((v.y - mu) * inv * gg.y + bb.y);
        o4.z = f2tf32((v.z - mu) * inv * gg.z + bb.z);
        o4.w = f2tf32((v.w - mu) * inv * gg.w + bb.w);
        *(float4*)(g_xln + (size_t)row * HD + lane * 4) = o4;
        return;
    }
    const int DX4 = NN * HD / 4;
    const int DV4 = NN * 3 * HD / 4;
    const int s1 = 128 * 128 / 4, s2 = 128 * 384 / 4, s3 = 64 * 384 / 4;
    const int s4 = 128 * 256 / 4, s5 = 256 * 128 / 4, s6 = 128 * 384 / 4;
    const int total = DX4 + DV4 + s1 + s2 + s3 + s4 + s5 + s6;
    int base = (blk - 4096) * 256 + tid;
    int stride = (gridDim.x - 4096) * 256;
    for (int i = base; i < total; i += stride) {
        int j = i;
        if (j < DX4) { ((float4*)g_dx)[j] = ((const float4*)x)[j]; continue; }
        j -= DX4;
        if (j < DV4) { ((float4*)g_dvec)[j] = ((const float4*)vec)[j]; continue; }
        j -= DV4;
        if (j < s1) { ((float4*)g_W1t)[j] = rnd4(((const float4*)W1)[j]); continue; }
        j -= s1;
        if (j < s2) { ((float4*)g_W2t)[j] = rnd4(((const float4*)W2)[j]); continue; }
        j -= s2;
        if (j < s3) { ((float4*)g_Wrt)[j] = rnd4(((const float4*)Wr)[j]); continue; }
        j -= s3;
        if (j < s4) { ((float4*)g_Wvt)[j] = rnd4(((const float4*)Wv)[j]); continue; }
        j -= s4;
        if (j < s5) { ((float4*)g_Wu1t)[j] = rnd4(((const float4*)Wu1)[j]); continue; }
        j -= s5;
        ((float4*)g_Wu2t)[j] = rnd4(((const float4*)Wu2)[j]);
    }
}

// ---------------------------------------------------------------------------
// Double-buffered tf32 MMA mainloop for node GEMMs (inputs pre-rounded).
// ---------------------------------------------------------------------------
template <int BM, int BN>
__device__ __forceinline__ void mma_loop(
    const float* __restrict__ A, int lda,
    const float* __restrict__ B, int ldb, int K,
    float* sm, float acc[2][8][4]) {
    const int BSW = BN + 8;
    const int ABUF = BM * ASW;
    const int BBUF = 32 * BSW;
    float* As = sm;
    float* Bs = sm + 2 * ABUF;
    int tid = threadIdx.x;
    int wid = tid >> 5, lane = tid & 31;
    int g = lane >> 2, t = lane & 3;
    const int WN = BN / 64;
    int wm = wid / WN, wn = wid % WN;
    int mbase = wm * 32;

    {
#pragma unroll
        for (int i = 0; i < BM / 32; i++) {
            int f = tid + i * 256;
            int row = f >> 3, c4 = (f & 7) * 4;
            cp16(As + row * ASW + c4, A + (size_t)row * lda + c4);
        }
#pragma unroll
        for (int i = 0; i < BN / 32; i++) {
            int f = tid + i * 256;
            int row = f / (BN / 4), c4 = (f % (BN / 4)) * 4;
            cp16(Bs + row * BSW + c4, B + (size_t)row * ldb + c4);
        }
        asm volatile("cp.async.commit_group;" ::: "memory");
    }

    int nk = K >> 5;
    for (int kc = 0; kc < nk; kc++) {
        if (kc + 1 < nk) {
            int k0 = (kc + 1) * 32;
            float* as = As + ((kc + 1) & 1) * ABUF;
            float* bs = Bs + ((kc + 1) & 1) * BBUF;
#pragma unroll
            for (int i = 0; i < BM / 32; i++) {
                int f = tid + i * 256;
                int row = f >> 3, c4 = (f & 7) * 4;
                cp16(as + row * ASW + c4, A + (size_t)row * lda + k0 + c4);
            }
#pragma unroll
            for (int i = 0; i < BN / 32; i++) {
                int f = tid + i * 256;
                int row = f / (BN / 4), c4 = (f % (BN / 4)) * 4;
                cp16(bs + row * BSW + c4, B + (size_t)(k0 + row) * ldb + c4);
            }
            asm volatile("cp.async.commit_group;" ::: "memory");
            asm volatile("cp.async.wait_group 1;" ::: "memory");
        } else {
            asm volatile("cp.async.wait_group 0;" ::: "memory");
        }
        __syncthreads();
        const float* as = As + (kc & 1) * ABUF;
        const float* bs = Bs + (kc & 1) * BBUF;
#pragma unroll
        for (int ks = 0; ks < 4; ks++) {
            int kk = ks * 8;
            uint32_t af[2][4];
#pragma unroll
            for (int mt = 0; mt < 2; mt++) {
                int r0 = mbase + mt * 16;
                af[mt][0] = __float_as_uint(as[(r0 + g) * ASW + kk + t]);
                af[mt][1] = __float_as_uint(as[(r0 + g + 8) * ASW + kk + t]);
                af[mt][2] = __float_as_uint(as[(r0 + g) * ASW + kk + t + 4]);
                af[mt][3] = __float_as_uint(as[(r0 + g + 8) * ASW + kk + t + 4]);
            }
#pragma unroll
            for (int nt = 0; nt < 8; nt++) {
                int cb = wn * 64 + nt * 8;
                uint32_t b0 = __float_as_uint(bs[(kk + t) * BSW + cb + g]);
                uint32_t b1 = __float_as_uint(bs[(kk + t + 4) * BSW + cb + g]);
#pragma unroll
                for (int mt = 0; mt < 2; mt++) mma8(acc[mt][nt], af[mt], b0, b1);
            }
        }
        __syncthreads();
    }
}

// edge MMA compute over fully-resident K=64 tiles -----------------------------
template <int BM, int BN>
__device__ __forceinline__ void edge_mma_compute(const float* As,
                                                 const float* Bs,
                                                 float acc[2][8][4]) {
    const int ESW = 68, BSW = BN + 8;
    int tid = threadIdx.x;
    int wid = tid >> 5, lane = tid & 31;
    int g = lane >> 2, t = lane & 3;
    const int WN = BN / 64;
    int wm = wid / WN, wn = wid % WN;
    int mbase = wm * 32;
#pragma unroll
    for (int ks = 0; ks < 8; ks++) {
        int kk = ks * 8;
        uint32_t af[2][4];
#pragma unroll
        for (int mt = 0; mt < 2; mt++) {
            int r0 = mbase + mt * 16;
            af[mt][0] = __float_as_uint(As[(r0 + g) * ESW + kk + t]);
            af[mt][1] = __float_as_uint(As[(r0 + g + 8) * ESW + kk + t]);
            af[mt][2] = __float_as_uint(As[(r0 + g) * ESW + kk + t + 4]);
            af[mt][3] = __float_as_uint(As[(r0 + g + 8) * ESW + kk + t + 4]);
        }
#pragma unroll
        for (int nt = 0; nt < 8; nt++) {
            int cb = wn * 64 + nt * 8;
            uint32_t b0 = __float_as_uint(Bs[(kk + t) * BSW + cb + g]);
            uint32_t b1 = __float_as_uint(Bs[(kk + t + 4) * BSW + cb + g]);
#pragma unroll
            for (int mt = 0; mt < 2; mt++) mma8(acc[mt][nt], af[mt], b0, b1);
        }
    }
}

#define ACC_INIT(acc)                                   \
    _Pragma("unroll") for (int i = 0; i < 2; i++)       \
    _Pragma("unroll") for (int j = 0; j < 8; j++)       \
    _Pragma("unroll") for (int k = 0; k < 4; k++) acc[i][j][k] = 0.f;

// ---------------------------------------------------------------------------
// Node GEMM: C = act(A @ B + bias), 128x128 tile. RND rounds output to tf32.
// ---------------------------------------------------------------------------
template <int ACT, int RND>
__global__ void __launch_bounds__(256, 2)
gemm_tc(const float* __restrict__ A, const float* __restrict__ B,
        const float* __restrict__ bias, float* __restrict__ C,
        int M, int N, int K) {
    extern __shared__ float sm[];
    float acc[2][8][4];
    ACC_INIT(acc)
    int bm = blockIdx.y * 128;
    int bn = blockIdx.x * 128;
    mma_loop<128, 128>(A + (size_t)bm * K, K, B + bn, N, K, sm, acc);

    int tid = threadIdx.x;
    int wid = tid >> 5, lane = tid & 31;
    int g = lane >> 2, t = lane & 3;
    int wm = wid >> 1, wn = wid & 1;
#pragma unroll
    for (int mt = 0; mt < 2; mt++) {
#pragma unroll
        for (int h = 0; h < 2; h++) {
            int r = bm + wm * 32 + mt * 16 + g + h * 8;
#pragma unroll
            for (int nt = 0; nt < 8; nt++) {
                int c = bn + wn * 64 + nt * 8 + 2 * t;
                float2 bb = *(const float2*)(bias + c);
                float vx = acc[mt][nt][2 * h + 0] + bb.x;
                float vy = acc[mt][nt][2 * h + 1] + bb.y;
                if (ACT) { vx = ssilu(vx); vy = ssilu(vy); }
                if (RND) { vx = f2tf32(vx); vy = f2tf32(vy); }
                float2 o = {vx, vy};
                *(float2*)(C + (size_t)r * N + c) = o;
            }
        }
    }
}

// ---------------------------------------------------------------------------
// vproj GEMM: g_vproj[3N,256] = rna(g_dvec)[3N,128] @ Wvt[128,256].
// ---------------------------------------------------------------------------
__global__ void __launch_bounds__(256, 2)
gemm_vproj(float* __restrict__ C) {
    extern __shared__ float sm[];
    float* As = sm;                 // 128 x 132
    float* Bs = sm + 128 * 132;     // 2 x 32 x 136
    int tid = threadIdx.x;
    int bm = blockIdx.y * 128;
    int bn = blockIdx.x * 128;
    const float* B = g_Wvt + bn;

#pragma unroll
    for (int i = 0; i < 4; i++) {
        int f = tid + i * 256;
        int row = f >> 5, c4 = (f & 31) * 4;
        cp16(Bs + row * 136 + c4, B + (size_t)row * 256 + c4);
    }
    asm volatile("cp.async.commit_group;" ::: "memory");

#pragma unroll
    for (int i = 0; i < 16; i++) {
        int f = tid + i * 256;
        int row = f >> 5, c4 = (f & 31) * 4;
        float4 v = rnd4(*(const float4*)(g_dvec + (size_t)(bm + row) * 128 + c4));
        *(float4*)(As + row * 132 + c4) = v;
    }

    int wid = tid >> 5, lane = tid & 31;
    int g = lane >> 2, t = lane & 3;
    int wm = wid >> 1, wn = wid & 1;
    int mbase = wm * 32;
    float acc[2][8][4];
    ACC_INIT(acc)

    for (int kc = 0; kc < 4; kc++) {
        if (kc < 3) {
            int k0 = (kc + 1) * 32;
            float* bs = Bs + ((kc + 1) & 1) * (32 * 136);
#pragma unroll
            for (int i = 0; i < 4; i++) {
                int f = tid + i * 256;
                int row = f >> 5, c4 = (f & 31) * 4;
                cp16(bs + row * 136 + c4, B + (size_t)(k0 + row) * 256 + c4);
            }
            asm volatile("cp.async.commit_group;" ::: "memory");
            asm volatile("cp.async.wait_group 1;" ::: "memory");
        } else {
            asm volatile("cp.async.wait_group 0;" ::: "memory");
        }
        __syncthreads();
        const float* bs = Bs + (kc & 1) * (32 * 136);
        int kg = kc * 32;
#pragma unroll
        for (int ks = 0; ks < 4; ks++) {
            int kk = ks * 8;
            uint32_t af[2][4];
#pragma unroll
            for (int mt = 0; mt < 2; mt++) {
                int r0 = mbase + mt * 16;
                af[mt][0] = __float_as_uint(As[(r0 + g) * 132 + kg + kk + t]);
                af[mt][1] = __float_as_uint(As[(r0 + g + 8) * 132 + kg + kk + t]);
                af[mt][2] = __float_as_uint(As[(r0 + g) * 132 + kg + kk + t + 4]);
                af[mt][3] = __float_as_uint(As[(r0 + g + 8) * 132 + kg + kk + t + 4]);
            }
#pragma unroll
            for (int nt = 0; nt < 8; nt++) {
                int cb = wn * 64 + nt * 8;
                uint32_t b0 = __float_as_uint(bs[(kk + t) * 136 + cb + g]);
                uint32_t b1 = __float_as_uint(bs[(kk + t + 4) * 136 + cb + g]);
#pragma unroll
                for (int mt = 0; mt < 2; mt++) mma8(acc[mt][nt], af[mt], b0, b1);
            }
        }
        __syncthreads();
    }

#pragma unroll
    for (int mt = 0; mt < 2; mt++) {
#pragma unroll
        for (int h = 0; h < 2; h++) {
            int r = bm + wm * 32 + mt * 16 + g + h * 8;
#pragma unroll
            for (int nt = 0; nt < 8; nt++) {
                int c = bn + wn * 64 + nt * 8 + 2 * t;
                float2 o = {acc[mt][nt][2 * h + 0], acc[mt][nt][2 * h + 1]};
                *(float2*)(C + (size_t)r * 256 + c) = o;
            }
        }
    }
}

// ---------------------------------------------------------------------------
// Merged edge kernel with ee-reuse interleaving:
//   group = blockIdx.x / 3 covers edges [group*128, group*128+128)
//   r = blockIdx.x % 3:  r==0 -> dx path (128 edges)
//                        r==1 -> dvec path, edges [group*128, +64)
//                        r==2 -> dvec path, edges [group*128+64, +64)
// The 3 blocks sharing the same ee rows launch adjacently -> L2 reuse.
// ---------------------------------------------------------------------------
__global__ void __launch_bounds__(256, 2)
edge_gemm_all(const float* __restrict__ ee, const float* __restrict__ br,
              const int* __restrict__ ei, const float* __restrict__ vec,
              const float* __restrict__ evec) {
    const int ESW = 68;
    extern __shared__ float sm[];
    __shared__ int s_src[128];
    __shared__ int s_dst[128];
    __shared__ float s_ev[3][64];
    int tid = threadIdx.x;
    int group = blockIdx.x / 3;
    int r = blockIdx.x - group * 3;

    if (r == 0) {
        // ----------------- dx path: 128 edges, BN=128 -----------------
        const int BSW = 136;
        float* As = sm;
        float* Bs = sm + 128 * ESW;
        int bm = group * 128;

#pragma unroll
        for (int i = 0; i < 8; i++) {
            int f = tid + i * 256;
            int row = f >> 5, c4 = (f & 31) * 4;
            cp16(Bs + row * BSW + c4, g_Wrt + (size_t)row * 384 + c4);
        }
        asm volatile("cp.async.commit_group;" ::: "memory");

        if (tid < 128) {
            s_src[tid] = ei[bm + tid];
            s_dst[tid] = ei[NE + bm + tid];
        }

#pragma unroll
        for (int i = 0; i < 8; i++) {
            int f = tid + i * 256;
            int row = f >> 4, c4 = (f & 15) * 4;
            float4 v = rnd4(*(const float4*)(ee + (size_t)(bm + row) * 64 + c4));
            *(float4*)(As + row * ESW + c4) = v;
        }
        asm volatile("cp.async.wait_group 0;" ::: "memory");
        __syncthreads();

        float acc[2][8][4];
        ACC_INIT(acc)
        edge_mma_compute<128, 128>(As, Bs, acc);
        __syncthreads();

        float* sbuf = sm;   // 128 x 132
        int wid = tid >> 5, lane = tid & 31;
        int g = lane >> 2, t = lane & 3;
        int wm = wid >> 1, wn = wid & 1;
#pragma unroll
        for (int mt = 0; mt < 2; mt++) {
#pragma unroll
            for (int h = 0; h < 2; h++) {
                int row = wm * 32 + mt * 16 + g + h * 8;
#pragma unroll
                for (int nt = 0; nt < 8; nt++) {
                    int col = wn * 64 + nt * 8 + 2 * t;
                    float2 bb = *(const float2*)(br + col);
                    sbuf[row * 132 + col]     = acc[mt][nt][2 * h + 0] + bb.x;
                    sbuf[row * 132 + col + 1] = acc[mt][nt][2 * h + 1] + bb.y;
                }
            }
        }
        __syncthreads();
#pragma unroll
        for (int i = 0; i < 16; i++) {
            int f = tid + i * 256;
            int e = f >> 5;
            int c4 = (f & 31) * 4;
            int src = s_src[e], dst = s_dst[e];
            float4 m = *(float4*)(sbuf + e * 132 + c4);
            float4 x1 = *(const float4*)(g_xh + (size_t)src * 384 + c4);
            m.x *= x1.x; m.y *= x1.y; m.z *= x1.z; m.w *= x1.w;
            red4(g_dx + (size_t)dst * HD + c4, m);
        }
    } else {
        // ----------------- dvec path: 64 edges, BN=256 -----------------
        const int BSW = 264;
        float* As = sm;
        float* Bs = sm + 64 * ESW;
        int bm = group * 128 + (r - 1) * 64;

#pragma unroll
        for (int i = 0; i < 16; i++) {
            int f = tid + i * 256;
            int row = f >> 6, c4 = (f & 63) * 4;
            cp16(Bs + row * BSW + c4, g_Wrt + 128 + (size_t)row * 384 + c4);
        }
        asm volatile("cp.async.commit_group;" ::: "memory");

        if (tid < 64) {
            s_src[tid] = ei[bm + tid];
            s_dst[tid] = ei[NE + bm + tid];
        }
        if (tid < 192) {
            int e = tid & 63;
            int c = tid >> 6;
            s_ev[c][e] = evec[(size_t)(bm + e) * 3 + c];
        }

#pragma unroll
        for (int i = 0; i < 4; i++) {
            int f = tid + i * 256;
            int row = f >> 4, c4 = (f & 15) * 4;
            float4 v = rnd4(*(const float4*)(ee + (size_t)(bm + row) * 64 + c4));
            *(float4*)(As + row * ESW + c4) = v;
        }
        asm volatile("cp.async.wait_group 0;" ::: "memory");
        __syncthreads();

        float acc[2][8][4];
        ACC_INIT(acc)
        edge_mma_compute<64, 256>(As, Bs, acc);
        __syncthreads();

        float* sbuf = sm;   // 64 x 260
        int wid = tid >> 5, lane = tid & 31;
        int g = lane >> 2, t = lane & 3;
        int wm = wid >> 2, wn = wid & 3;
#pragma unroll
        for (int mt = 0; mt < 2; mt++) {
#pragma unroll
            for (int h = 0; h < 2; h++) {
                int row = wm * 32 + mt * 16 + g + h * 8;
#pragma unroll
                for (int nt = 0; nt < 8; nt++) {
                    int col = wn * 64 + nt * 8 + 2 * t;
                    float2 bb = *(const float2*)(br + 128 + col);
                    sbuf[row * 260 + col]     = acc[mt][nt][2 * h + 0] + bb.x;
                    sbuf[row * 260 + col + 1] = acc[mt][nt][2 * h + 1] + bb.y;
                }
            }
        }
        __syncthreads();
#pragma unroll
        for (int i = 0; i < 8; i++) {
            int f = tid + i * 256;
            int e = f >> 5;
            int c4 = (f & 31) * 4;
            int src = s_src[e], dst = s_dst[e];
            float ev0 = s_ev[0][e], ev1 = s_ev[1][e], ev2 = s_ev[2][e];
            float4 r2 = *(float4*)(sbuf + e * 260 + c4);
            float4 r3 = *(float4*)(sbuf + e * 260 + 128 + c4);
            const float* xhp = g_xh + (size_t)src * 384;
            float4 x2 = *(const float4*)(xhp + 128 + c4);
            float4 x3 = *(const float4*)(xhp + 256 + c4);
            float4 m2, m3;
            m2.x = r2.x * x2.x * C_INV_SQRT_3; m2.y = r2.y * x2.y * C_INV_SQRT_3;
            m2.z = r2.z * x2.z * C_INV_SQRT_3; m2.w = r2.w * x2.w * C_INV_SQRT_3;
            m3.x = r3.x * x3.x; m3.y = r3.y * x3.y;
            m3.z = r3.z * x3.z; m3.w = r3.w * x3.w;
            const float* vp = vec + (size_t)src * 384;
            float* dvp = g_dvec + (size_t)dst * 384;
#pragma unroll
            for (int c = 0; c < 3; c++) {
                float ev = (c == 0) ? ev0 : ((c == 1) ? ev1 : ev2);
                float4 vv = *(const float4*)(vp + c * 128 + c4);
                float4 msg;
                msg.x = (vv.x * m2.x + m3.x * ev) * C_INV_SQRT_H;
                msg.y = (vv.y * m2.y + m3.y * ev) * C_INV_SQRT_H;
                msg.z = (vv.z * m2.z + m3.z * ev) * C_INV_SQRT_H;
                msg.w = (vv.w * m2.w + m3.w * ev) * C_INV_SQRT_H;
                red4(dvp + c * 128 + c4, msg);
            }
        }
    }
}

// ---------------------------------------------------------------------------
__global__ void dotnorm_kernel() {
    int i = blockIdx.x * blockDim.x + threadIdx.x;
    if (i >= NN * HD) return;
    int n = i >> 7;
    int h = i & 127;
    const float* vp = g_vproj + (size_t)n * 768;
    float d = 0.f, s = 0.f;
#pragma unroll
    for (int c = 0; c < 3; c++) {
        float v1 = vp[c * 256 + h];
        float v2 = vp[c * 256 + 128 + h];
        d += v1 * v2;
        s += v2 * v2;
    }
    float xn = g_dx[i] * C_INV_SQRT_2;
    g_vecdot[i] = d * C_INV_SQRT_H;
    g_cat[(size_t)n * 256 + h] = f2tf32(xn);
    g_cat[(size_t)n * 256 + 128 + h] = f2tf32(sqrtf(s + 1e-8f));
}

// ---------------------------------------------------------------------------
__global__ void finalize_kernel(float* __restrict__ out) {
    int i = blockIdx.x * blockDim.x + threadIdx.x;
    if (i >= NN * HD) return;
    int n = i >> 7;
    int h = i & 127;
    const float* hb = g_hbuf + (size_t)n * 384;
    float xv1 = hb[h];
    float xv2 = hb[128 + h];
    float xv3 = hb[256 + h];
    float* out_vec = out;
    float* out_x = out + (size_t)NN * 3 * HD;
    float xn = g_dx[i] * C_INV_SQRT_2;
    out_x[i] = xn + (xv1 + xv2 * g_vecdot[i]) * C_INV_SQRT_2;
#pragma unroll
    for (int c = 0; c < 3; c++) {
        size_t idx = (size_t)n * 384 + c * HD + h;
        out_vec[idx] = g_dvec[idx] + xv3 * g_vproj[(size_t)n * 768 + c * 256 + h];
    }
}

// ---------------------------------------------------------------------------
extern "C" void kernel_launch(void* const* d_in, const int* in_sizes, int n_in,
                              void* d_out, int out_size) {
    const float* x    = (const float*)d_in[0];
    const float* vec  = (const float*)d_in[1];
    const int*   ei   = (const int*)d_in[2];
    const float* ee   = (const float*)d_in[3];
    const float* evec = (const float*)d_in[4];
    const float* ln_g = (const float*)d_in[5];
    const float* ln_b = (const float*)d_in[6];
    const float* W1   = (const float*)d_in[7];
    const float* b1   = (const float*)d_in[8];
    const float* W2   = (const float*)d_in[9];
    const float* b2   = (const float*)d_in[10];
    const float* Wr   = (const float*)d_in[11];
    const float* br   = (const float*)d_in[12];
    const float* Wv   = (const float*)d_in[13];
    const float* Wu1  = (const float*)d_in[14];
    const float* bu1  = (const float*)d_in[15];
    const float* Wu2  = (const float*)d_in[16];
    const float* bu2  = (const float*)d_in[17];

    float* out = (float*)d_out;

    float* xln = nullptr;     cudaGetSymbolAddress((void**)&xln, g_xln);
    float* t1 = nullptr;      cudaGetSymbolAddress((void**)&t1, g_t1);
    float* vproj = nullptr;   cudaGetSymbolAddress((void**)&vproj, g_vproj);
    float* cat = nullptr;     cudaGetSymbolAddress((void**)&cat, g_cat);
    float* u = nullptr;       cudaGetSymbolAddress((void**)&u, g_u);
    float* hbuf = nullptr;    cudaGetSymbolAddress((void**)&hbuf, g_hbuf);
    float* xh = nullptr;      cudaGetSymbolAddress((void**)&xh, g_xh);
    float* w1t = nullptr;     cudaGetSymbolAddress((void**)&w1t, g_W1t);
    float* w2t = nullptr;     cudaGetSymbolAddress((void**)&w2t, g_W2t);
    float* wu1t = nullptr;    cudaGetSymbolAddress((void**)&wu1t, g_Wu1t);
    float* wu2t = nullptr;    cudaGetSymbolAddress((void**)&wu2t, g_Wu2t);

    const int SMEM_NODE  = (2 * 128 * ASW + 2 * 32 * 136) * 4;  // 71680
    const int SMEM_EDGE  = (64 * 68 + 64 * 264) * 4;            // 84992 (max path)
    const int SMEM_VPROJ = (128 * 132 + 2 * 32 * 136) * 4;      // 102400

    cudaFuncSetAttribute((const void*)gemm_tc<0, 0>,
                         cudaFuncAttributeMaxDynamicSharedMemorySize, SMEM_NODE);
    cudaFuncSetAttribute((const void*)gemm_tc<1, 1>,
                         cudaFuncAttributeMaxDynamicSharedMemorySize, SMEM_NODE);
    cudaFuncSetAttribute((const void*)edge_gemm_all,
                         cudaFuncAttributeMaxDynamicSharedMemorySize, SMEM_EDGE);
    cudaFuncSetAttribute((const void*)gemm_vproj,
                         cudaFuncAttributeMaxDynamicSharedMemorySize, SMEM_VPROJ);

    // 1. prep: LN + accumulator init (dx=x, dvec=vec) + weight rounding
    prep_kernel<<<4096 + 4096, 256>>>(x, vec, ln_g, ln_b,
                                      W1, W2, Wr, Wv, Wu1, Wu2);

    // 2. t1 = rna(scaled_silu(xln @ W1 + b1))
    gemm_tc<1, 1><<<dim3(1, NN / 128), 256, SMEM_NODE>>>(xln, w1t, b1, t1,
                                                         NN, 128, 128);
    // 3. xh = t1 @ W2 + b2
    gemm_tc<0, 0><<<dim3(3, NN / 128), 256, SMEM_NODE>>>(t1, w2t, b2, xh,
                                                         NN, 384, 128);

    // 4. merged edge kernel, ee-reuse interleaved (3 blocks per 128 edges)
    edge_gemm_all<<<12288, 256, SMEM_EDGE>>>(ee, br, ei, vec, evec);

    // 5. vproj = rna(vec_new) @ Wv
    gemm_vproj<<<dim3(2, (3 * NN) / 128), 256, SMEM_VPROJ>>>(vproj);

    // 6. x_new + vec_dot / vec2_norm / cat
    dotnorm_kernel<<<(NN * HD) / 256, 256>>>();

    // 7. u = rna(scaled_silu(cat @ Wu1 + bu1))
    gemm_tc<1, 1><<<dim3(1, NN / 128), 256, SMEM_NODE>>>(cat, wu1t, bu1, u,
                                                         NN, 128, 256);
    // 8. hbuf = u @ Wu2 + bu2
    gemm_tc<0, 0><<<dim3(3, NN / 128), 256, SMEM_NODE>>>(u, wu2t, bu2, hbuf,
                                                         NN, 384, 128);

    // 9. finalize
    finalize_kernel<<<(NN * HD) / 256, 256>>>(out);
}

// round 15
// speedup vs baseline: 1.0885x; 1.0885x over previous
#include <cuda_runtime.h>
#include <math.h>
#include <stdint.h>

#define NN 32768
#define NE 524288
#define HD 128
#define ASW 36

__device__ __forceinline__ float ssilu(float v) {
    return v / ((1.0f + __expf(-v)) * 0.6f);
}
__device__ __forceinline__ float f2tf32(float x) {
    float r;
    asm("cvt.rna.tf32.f32 %0, %1;" : "=f"(r) : "f"(x));
    return r;
}
__device__ __forceinline__ float4 rnd4(float4 v) {
    v.x = f2tf32(v.x); v.y = f2tf32(v.y);
    v.z = f2tf32(v.z); v.w = f2tf32(v.w);
    return v;
}

// scratch ------------------------------------------------------------------
static __device__ float g_xln[NN * HD];
static __device__ float g_t1[NN * HD];
static __device__ float g_xh[NN * 3 * HD];
static __device__ float g_dx[NN * HD];        // init = x, accumulates dx
static __device__ float g_dvec[NN * 3 * HD];  // init = vec, accumulates dvec
static __device__ float g_vproj[NN * 3 * 2 * HD];
static __device__ float g_vecdot[NN * HD];
static __device__ float g_cat[NN * 2 * HD];
static __device__ float g_u[NN * HD];
static __device__ float g_hbuf[NN * 3 * HD];
static __device__ float g_W1t[128 * 128];
static __device__ float g_W2t[128 * 384];
static __device__ float g_Wrt[64 * 384];
static __device__ float g_Wvt[128 * 256];
static __device__ float g_Wu1t[256 * 128];
static __device__ float g_Wu2t[128 * 384];

__constant__ float C_INV_SQRT_3 = 0.57735026918962576451f;
__constant__ float C_INV_SQRT_H = 0.08838834764831844055f;
__constant__ float C_INV_SQRT_2 = 0.70710678118654752440f;

// ---------------------------------------------------------------------------
__device__ __forceinline__ void cp16(float* s, const float* g) {
    uint32_t sa = (uint32_t)__cvta_generic_to_shared(s);
    asm volatile("cp.async.cg.shared.global [%0], [%1], 16;"
                 :: "r"(sa), "l"(g) : "memory");
}
__device__ __forceinline__ void mma8(float c[4], const uint32_t a[4],
                                     uint32_t b0, uint32_t b1) {
    asm volatile(
        "mma.sync.aligned.m16n8k8.row.col.f32.tf32.tf32.f32 "
        "{%0,%1,%2,%3}, {%4,%5,%6,%7}, {%8,%9}, {%0,%1,%2,%3};"
        : "+f"(c[0]), "+f"(c[1]), "+f"(c[2]), "+f"(c[3])
        : "r"(a[0]), "r"(a[1]), "r"(a[2]), "r"(a[3]), "r"(b0), "r"(b1));
}
__device__ __forceinline__ void red4(float* addr, float4 v) {
    asm volatile("red.global.add.v4.f32 [%0], {%1, %2, %3, %4};"
                 :: "l"(addr), "f"(v.x), "f"(v.y), "f"(v.z), "f"(v.w)
                 : "memory");
}
// evict-first streaming load of a float4 (for stream-once data like ee)
__device__ __forceinline__ float4 ld_cs4(const float* p) {
    float4 v;
    asm volatile("ld.global.cs.v4.f32 {%0,%1,%2,%3}, [%4];"
                 : "=f"(v.x), "=f"(v.y), "=f"(v.z), "=f"(v.w) : "l"(p));
    return v;
}

// ---------------------------------------------------------------------------
// prep_kernel: blocks [0,4096) LayerNorm; rest: dx=x, dvec=vec, weight round.
// ---------------------------------------------------------------------------
__global__ void prep_kernel(const float* __restrict__ x,
                            const float* __restrict__ vec,
                            const float* __restrict__ lng,
                            const float* __restrict__ lnb,
                            const float* __restrict__ W1,
                            const float* __restrict__ W2,
                            const float* __restrict__ Wr,
                            const float* __restrict__ Wv,
                            const float* __restrict__ Wu1,
                            const float* __restrict__ Wu2) {
    int blk = blockIdx.x;
    int tid = threadIdx.x;
    if (blk < 4096) {
        int row = blk * 8 + (tid >> 5);
        int lane = tid & 31;
        float4 v = *(const float4*)(x + (size_t)row * HD + lane * 4);
        float s = v.x + v.y + v.z + v.w;
        float s2 = v.x * v.x + v.y * v.y + v.z * v.z + v.w * v.w;
#pragma unroll
        for (int o = 16; o > 0; o >>= 1) {
            s += __shfl_xor_sync(0xffffffffu, s, o);
            s2 += __shfl_xor_sync(0xffffffffu, s2, o);
        }
        float mu = s * (1.0f / HD);
        float var = s2 * (1.0f / HD) - mu * mu;
        float inv = rsqrtf(var + 1e-5f);
        float4 gg = *(const float4*)(lng + lane * 4);
        float4 bb = *(const float4*)(lnb + lane * 4);
        float4 o4;
        o4.x = f2tf32((v.x - mu) * inv * gg.x + bb.x);
        o4.y = f2tf32((v.y - mu) * inv * gg.y + bb.y);
        o4.z = f2tf32((v.z - mu) * inv * gg.z + bb.z);
        o4.w = f2tf32((v.w - mu) * inv * gg.w + bb.w);
        *(float4*)(g_xln + (size_t)row * HD + lane * 4) = o4;
        return;
    }
    const int DX4 = NN * HD / 4;
    const int DV4 = NN * 3 * HD / 4;
    const int s1 = 128 * 128 / 4, s2 = 128 * 384 / 4, s3 = 64 * 384 / 4;
    const int s4 = 128 * 256 / 4, s5 = 256 * 128 / 4, s6 = 128 * 384 / 4;
    const int total = DX4 + DV4 + s1 + s2 + s3 + s4 + s5 + s6;
    int base = (blk - 4096) * 256 + tid;
    int stride = (gridDim.x - 4096) * 256;
    for (int i = base; i < total; i += stride) {
        int j = i;
        if (j < DX4) { ((float4*)g_dx)[j] = ((const float4*)x)[j]; continue; }
        j -= DX4;
        if (j < DV4) { ((float4*)g_dvec)[j] = ((const float4*)vec)[j]; continue; }
        j -= DV4;
        if (j < s1) { ((float4*)g_W1t)[j] = rnd4(((const float4*)W1)[j]); continue; }
        j -= s1;
        if (j < s2) { ((float4*)g_W2t)[j] = rnd4(((const float4*)W2)[j]); continue; }
        j -= s2;
        if (j < s3) { ((float4*)g_Wrt)[j] = rnd4(((const float4*)Wr)[j]); continue; }
        j -= s3;
        if (j < s4) { ((float4*)g_Wvt)[j] = rnd4(((const float4*)Wv)[j]); continue; }
        j -= s4;
        if (j < s5) { ((float4*)g_Wu1t)[j] = rnd4(((const float4*)Wu1)[j]); continue; }
        j -= s5;
        ((float4*)g_Wu2t)[j] = rnd4(((const float4*)Wu2)[j]);
    }
}

// ---------------------------------------------------------------------------
// Double-buffered tf32 MMA mainloop for node GEMMs (inputs pre-rounded).
// ---------------------------------------------------------------------------
template <int BM, int BN>
__device__ __forceinline__ void mma_loop(
    const float* __restrict__ A, int lda,
    const float* __restrict__ B, int ldb, int K,
    float* sm, float acc[2][8][4]) {
    const int BSW = BN + 8;
    const int ABUF = BM * ASW;
    const int BBUF = 32 * BSW;
    float* As = sm;
    float* Bs = sm + 2 * ABUF;
    int tid = threadIdx.x;
    int wid = tid >> 5, lane = tid & 31;
    int g = lane >> 2, t = lane & 3;
    const int WN = BN / 64;
    int wm = wid / WN, wn = wid % WN;
    int mbase = wm * 32;

    {
#pragma unroll
        for (int i = 0; i < BM / 32; i++) {
            int f = tid + i * 256;
            int row = f >> 3, c4 = (f & 7) * 4;
            cp16(As + row * ASW + c4, A + (size_t)row * lda + c4);
        }
#pragma unroll
        for (int i = 0; i < BN / 32; i++) {
            int f = tid + i * 256;
            int row = f / (BN / 4), c4 = (f % (BN / 4)) * 4;
            cp16(Bs + row * BSW + c4, B + (size_t)row * ldb + c4);
        }
        asm volatile("cp.async.commit_group;" ::: "memory");
    }

    int nk = K >> 5;
    for (int kc = 0; kc < nk; kc++) {
        if (kc + 1 < nk) {
            int k0 = (kc + 1) * 32;
            float* as = As + ((kc + 1) & 1) * ABUF;
            float* bs = Bs + ((kc + 1) & 1) * BBUF;
#pragma unroll
            for (int i = 0; i < BM / 32; i++) {
                int f = tid + i * 256;
                int row = f >> 3, c4 = (f & 7) * 4;
                cp16(as + row * ASW + c4, A + (size_t)row * lda + k0 + c4);
            }
#pragma unroll
            for (int i = 0; i < BN / 32; i++) {
                int f = tid + i * 256;
                int row = f / (BN / 4), c4 = (f % (BN / 4)) * 4;
                cp16(bs + row * BSW + c4, B + (size_t)(k0 + row) * ldb + c4);
            }
            asm volatile("cp.async.commit_group;" ::: "memory");
            asm volatile("cp.async.wait_group 1;" ::: "memory");
        } else {
            asm volatile("cp.async.wait_group 0;" ::: "memory");
        }
        __syncthreads();
        const float* as = As + (kc & 1) * ABUF;
        const float* bs = Bs + (kc & 1) * BBUF;
#pragma unroll
        for (int ks = 0; ks < 4; ks++) {
            int kk = ks * 8;
            uint32_t af[2][4];
#pragma unroll
            for (int mt = 0; mt < 2; mt++) {
                int r0 = mbase + mt * 16;
                af[mt][0] = __float_as_uint(as[(r0 + g) * ASW + kk + t]);
                af[mt][1] = __float_as_uint(as[(r0 + g + 8) * ASW + kk + t]);
                af[mt][2] = __float_as_uint(as[(r0 + g) * ASW + kk + t + 4]);
                af[mt][3] = __float_as_uint(as[(r0 + g + 8) * ASW + kk + t + 4]);
            }
#pragma unroll
            for (int nt = 0; nt < 8; nt++) {
                int cb = wn * 64 + nt * 8;
                uint32_t b0 = __float_as_uint(bs[(kk + t) * BSW + cb + g]);
                uint32_t b1 = __float_as_uint(bs[(kk + t + 4) * BSW + cb + g]);
#pragma unroll
                for (int mt = 0; mt < 2; mt++) mma8(acc[mt][nt], af[mt], b0, b1);
            }
        }
        __syncthreads();
    }
}

// edge MMA compute over fully-resident K=64 tiles -----------------------------
template <int BM, int BN>
__device__ __forceinline__ void edge_mma_compute(const float* As,
                                                 const float* Bs,
                                                 float acc[2][8][4]) {
    const int ESW = 68, BSW = BN + 8;
    int tid = threadIdx.x;
    int wid = tid >> 5, lane = tid & 31;
    int g = lane >> 2, t = lane & 3;
    const int WN = BN / 64;
    int wm = wid / WN, wn = wid % WN;
    int mbase = wm * 32;
#pragma unroll
    for (int ks = 0; ks < 8; ks++) {
        int kk = ks * 8;
        uint32_t af[2][4];
#pragma unroll
        for (int mt = 0; mt < 2; mt++) {
            int r0 = mbase + mt * 16;
            af[mt][0] = __float_as_uint(As[(r0 + g) * ESW + kk + t]);
            af[mt][1] = __float_as_uint(As[(r0 + g + 8) * ESW + kk + t]);
            af[mt][2] = __float_as_uint(As[(r0 + g) * ESW + kk + t + 4]);
            af[mt][3] = __float_as_uint(As[(r0 + g + 8) * ESW + kk + t + 4]);
        }
#pragma unroll
        for (int nt = 0; nt < 8; nt++) {
            int cb = wn * 64 + nt * 8;
            uint32_t b0 = __float_as_uint(Bs[(kk + t) * BSW + cb + g]);
            uint32_t b1 = __float_as_uint(Bs[(kk + t + 4) * BSW + cb + g]);
#pragma unroll
            for (int mt = 0; mt < 2; mt++) mma8(acc[mt][nt], af[mt], b0, b1);
        }
    }
}

#define ACC_INIT(acc)                                   \
    _Pragma("unroll") for (int i = 0; i < 2; i++)       \
    _Pragma("unroll") for (int j = 0; j < 8; j++)       \
    _Pragma("unroll") for (int k = 0; k < 4; k++) acc[i][j][k] = 0.f;

// ---------------------------------------------------------------------------
// Node GEMM: C = act(A @ B + bias), 128x128 tile. RND rounds output to tf32.
// ---------------------------------------------------------------------------
template <int ACT, int RND>
__global__ void __launch_bounds__(256, 2)
gemm_tc(const float* __restrict__ A, const float* __restrict__ B,
        const float* __restrict__ bias, float* __restrict__ C,
        int M, int N, int K) {
    extern __shared__ float sm[];
    float acc[2][8][4];
    ACC_INIT(acc)
    int bm = blockIdx.y * 128;
    int bn = blockIdx.x * 128;
    mma_loop<128, 128>(A + (size_t)bm * K, K, B + bn, N, K, sm, acc);

    int tid = threadIdx.x;
    int wid = tid >> 5, lane = tid & 31;
    int g = lane >> 2, t = lane & 3;
    int wm = wid >> 1, wn = wid & 1;
#pragma unroll
    for (int mt = 0; mt < 2; mt++) {
#pragma unroll
        for (int h = 0; h < 2; h++) {
            int r = bm + wm * 32 + mt * 16 + g + h * 8;
#pragma unroll
            for (int nt = 0; nt < 8; nt++) {
                int c = bn + wn * 64 + nt * 8 + 2 * t;
                float2 bb = *(const float2*)(bias + c);
                float vx = acc[mt][nt][2 * h + 0] + bb.x;
                float vy = acc[mt][nt][2 * h + 1] + bb.y;
                if (ACT) { vx = ssilu(vx); vy = ssilu(vy); }
                if (RND) { vx = f2tf32(vx); vy = f2tf32(vy); }
                float2 o = {vx, vy};
                *(float2*)(C + (size_t)r * N + c) = o;
            }
        }
    }
}

// ---------------------------------------------------------------------------
// vproj GEMM: g_vproj[3N,256] = rna(g_dvec)[3N,128] @ Wvt[128,256].
// ---------------------------------------------------------------------------
__global__ void __launch_bounds__(256, 2)
gemm_vproj(float* __restrict__ C) {
    extern __shared__ float sm[];
    float* As = sm;                 // 128 x 132
    float* Bs = sm + 128 * 132;     // 2 x 32 x 136
    int tid = threadIdx.x;
    int bm = blockIdx.y * 128;
    int bn = blockIdx.x * 128;
    const float* B = g_Wvt + bn;

#pragma unroll
    for (int i = 0; i < 4; i++) {
        int f = tid + i * 256;
        int row = f >> 5, c4 = (f & 31) * 4;
        cp16(Bs + row * 136 + c4, B + (size_t)row * 256 + c4);
    }
    asm volatile("cp.async.commit_group;" ::: "memory");

#pragma unroll
    for (int i = 0; i < 16; i++) {
        int f = tid + i * 256;
        int row = f >> 5, c4 = (f & 31) * 4;
        float4 v = rnd4(*(const float4*)(g_dvec + (size_t)(bm + row) * 128 + c4));
        *(float4*)(As + row * 132 + c4) = v;
    }

    int wid = tid >> 5, lane = tid & 31;
    int g = lane >> 2, t = lane & 3;
    int wm = wid >> 1, wn = wid & 1;
    int mbase = wm * 32;
    float acc[2][8][4];
    ACC_INIT(acc)

    for (int kc = 0; kc < 4; kc++) {
        if (kc < 3) {
            int k0 = (kc + 1) * 32;
            float* bs = Bs + ((kc + 1) & 1) * (32 * 136);
#pragma unroll
            for (int i = 0; i < 4; i++) {
                int f = tid + i * 256;
                int row = f >> 5, c4 = (f & 31) * 4;
                cp16(bs + row * 136 + c4, B + (size_t)(k0 + row) * 256 + c4);
            }
            asm volatile("cp.async.commit_group;" ::: "memory");
            asm volatile("cp.async.wait_group 1;" ::: "memory");
        } else {
            asm volatile("cp.async.wait_group 0;" ::: "memory");
        }
        __syncthreads();
        const float* bs = Bs + (kc & 1) * (32 * 136);
        int kg = kc * 32;
#pragma unroll
        for (int ks = 0; ks < 4; ks++) {
            int kk = ks * 8;
            uint32_t af[2][4];
#pragma unroll
            for (int mt = 0; mt < 2; mt++) {
                int r0 = mbase + mt * 16;
                af[mt][0] = __float_as_uint(As[(r0 + g) * 132 + kg + kk + t]);
                af[mt][1] = __float_as_uint(As[(r0 + g + 8) * 132 + kg + kk + t]);
                af[mt][2] = __float_as_uint(As[(r0 + g) * 132 + kg + kk + t + 4]);
                af[mt][3] = __float_as_uint(As[(r0 + g + 8) * 132 + kg + kk + t + 4]);
            }
#pragma unroll
            for (int nt = 0; nt < 8; nt++) {
                int cb = wn * 64 + nt * 8;
                uint32_t b0 = __float_as_uint(bs[(kk + t) * 136 + cb + g]);
                uint32_t b1 = __float_as_uint(bs[(kk + t + 4) * 136 + cb + g]);
#pragma unroll
                for (int mt = 0; mt < 2; mt++) mma8(acc[mt][nt], af[mt], b0, b1);
            }
        }
        __syncthreads();
    }

#pragma unroll
    for (int mt = 0; mt < 2; mt++) {
#pragma unroll
        for (int h = 0; h < 2; h++) {
            int r = bm + wm * 32 + mt * 16 + g + h * 8;
#pragma unroll
            for (int nt = 0; nt < 8; nt++) {
                int c = bn + wn * 64 + nt * 8 + 2 * t;
                float2 o = {acc[mt][nt][2 * h + 0], acc[mt][nt][2 * h + 1]};
                *(float2*)(C + (size_t)r * 256 + c) = o;
            }
        }
    }
}

// ---------------------------------------------------------------------------
// Merged edge kernel (R13 segregated layout): blocks [0,4096) dx path;
// blocks [4096,12288) dvec path. ee staged with evict-first loads.
// ---------------------------------------------------------------------------
__global__ void __launch_bounds__(256, 2)
edge_gemm_all(const float* __restrict__ ee, const float* __restrict__ br,
              const int* __restrict__ ei, const float* __restrict__ vec,
              const float* __restrict__ evec) {
    const int ESW = 68;
    extern __shared__ float sm[];
    __shared__ int s_src[128];
    __shared__ int s_dst[128];
    __shared__ float s_ev[3][64];
    int tid = threadIdx.x;

    if (blockIdx.x < 4096) {
        // ----------------- dx path: 128 edges, BN=128 -----------------
        const int BSW = 136;
        float* As = sm;
        float* Bs = sm + 128 * ESW;
        int bm = blockIdx.x * 128;

#pragma unroll
        for (int i = 0; i < 8; i++) {
            int f = tid + i * 256;
            int row = f >> 5, c4 = (f & 31) * 4;
            cp16(Bs + row * BSW + c4, g_Wrt + (size_t)row * 384 + c4);
        }
        asm volatile("cp.async.commit_group;" ::: "memory");

        if (tid < 128) {
            s_src[tid] = ei[bm + tid];
            s_dst[tid] = ei[NE + bm + tid];
        }

#pragma unroll
        for (int i = 0; i < 8; i++) {
            int f = tid + i * 256;
            int row = f >> 4, c4 = (f & 15) * 4;
            float4 v = rnd4(ld_cs4(ee + (size_t)(bm + row) * 64 + c4));
            *(float4*)(As + row * ESW + c4) = v;
        }
        asm volatile("cp.async.wait_group 0;" ::: "memory");
        __syncthreads();

        float acc[2][8][4];
        ACC_INIT(acc)
        edge_mma_compute<128, 128>(As, Bs, acc);
        __syncthreads();

        float* sbuf = sm;   // 128 x 132
        int wid = tid >> 5, lane = tid & 31;
        int g = lane >> 2, t = lane & 3;
        int wm = wid >> 1, wn = wid & 1;
#pragma unroll
        for (int mt = 0; mt < 2; mt++) {
#pragma unroll
            for (int h = 0; h < 2; h++) {
                int row = wm * 32 + mt * 16 + g + h * 8;
#pragma unroll
                for (int nt = 0; nt < 8; nt++) {
                    int col = wn * 64 + nt * 8 + 2 * t;
                    float2 bb = *(const float2*)(br + col);
                    sbuf[row * 132 + col]     = acc[mt][nt][2 * h + 0] + bb.x;
                    sbuf[row * 132 + col + 1] = acc[mt][nt][2 * h + 1] + bb.y;
                }
            }
        }
        __syncthreads();
#pragma unroll
        for (int i = 0; i < 16; i++) {
            int f = tid + i * 256;
            int e = f >> 5;
            int c4 = (f & 31) * 4;
            int src = s_src[e], dst = s_dst[e];
            float4 m = *(float4*)(sbuf + e * 132 + c4);
            float4 x1 = *(const float4*)(g_xh + (size_t)src * 384 + c4);
            m.x *= x1.x; m.y *= x1.y; m.z *= x1.z; m.w *= x1.w;
            red4(g_dx + (size_t)dst * HD + c4, m);
        }
    } else {
        // ----------------- dvec path: 64 edges, BN=256 -----------------
        const int BSW = 264;
        float* As = sm;
        float* Bs = sm + 64 * ESW;
        int bm = (blockIdx.x - 4096) * 64;

#pragma unroll
        for (int i = 0; i < 16; i++) {
            int f = tid + i * 256;
            int row = f >> 6, c4 = (f & 63) * 4;
            cp16(Bs + row * BSW + c4, g_Wrt + 128 + (size_t)row * 384 + c4);
        }
        asm volatile("cp.async.commit_group;" ::: "memory");

        if (tid < 64) {
            s_src[tid] = ei[bm + tid];
            s_dst[tid] = ei[NE + bm + tid];
        }
        if (tid < 192) {
            int e = tid & 63;
            int c = tid >> 6;
            s_ev[c][e] = evec[(size_t)(bm + e) * 3 + c];
        }

#pragma unroll
        for (int i = 0; i < 4; i++) {
            int f = tid + i * 256;
            int row = f >> 4, c4 = (f & 15) * 4;
            float4 v = rnd4(ld_cs4(ee + (size_t)(bm + row) * 64 + c4));
            *(float4*)(As + row * ESW + c4) = v;
        }
        asm volatile("cp.async.wait_group 0;" ::: "memory");
        __syncthreads();

        float acc[2][8][4];
        ACC_INIT(acc)
        edge_mma_compute<64, 256>(As, Bs, acc);
        __syncthreads();

        float* sbuf = sm;   // 64 x 260
        int wid = tid >> 5, lane = tid & 31;
        int g = lane >> 2, t = lane & 3;
        int wm = wid >> 2, wn = wid & 3;
#pragma unroll
        for (int mt = 0; mt < 2; mt++) {
#pragma unroll
            for (int h = 0; h < 2; h++) {
                int row = wm * 32 + mt * 16 + g + h * 8;
#pragma unroll
                for (int nt = 0; nt < 8; nt++) {
                    int col = wn * 64 + nt * 8 + 2 * t;
                    float2 bb = *(const float2*)(br + 128 + col);
                    sbuf[row * 260 + col]     = acc[mt][nt][2 * h + 0] + bb.x;
                    sbuf[row * 260 + col + 1] = acc[mt][nt][2 * h + 1] + bb.y;
                }
            }
        }
        __syncthreads();
#pragma unroll
        for (int i = 0; i < 8; i++) {
            int f = tid + i * 256;
            int e = f >> 5;
            int c4 = (f & 31) * 4;
            int src = s_src[e], dst = s_dst[e];
            float ev0 = s_ev[0][e], ev1 = s_ev[1][e], ev2 = s_ev[2][e];
            float4 r2 = *(float4*)(sbuf + e * 260 + c4);
            float4 r3 = *(float4*)(sbuf + e * 260 + 128 + c4);
            const float* xhp = g_xh + (size_t)src * 384;
            float4 x2 = *(const float4*)(xhp + 128 + c4);
            float4 x3 = *(const float4*)(xhp + 256 + c4);
            float4 m2, m3;
            m2.x = r2.x * x2.x * C_INV_SQRT_3; m2.y = r2.y * x2.y * C_INV_SQRT_3;
            m2.z = r2.z * x2.z * C_INV_SQRT_3; m2.w = r2.w * x2.w * C_INV_SQRT_3;
            m3.x = r3.x * x3.x; m3.y = r3.y * x3.y;
            m3.z = r3.z * x3.z; m3.w = r3.w * x3.w;
            const float* vp = vec + (size_t)src * 384;
            float* dvp = g_dvec + (size_t)dst * 384;
#pragma unroll
            for (int c = 0; c < 3; c++) {
                float ev = (c == 0) ? ev0 : ((c == 1) ? ev1 : ev2);
                float4 vv = *(const float4*)(vp + c * 128 + c4);
                float4 msg;
                msg.x = (vv.x * m2.x + m3.x * ev) * C_INV_SQRT_H;
                msg.y = (vv.y * m2.y + m3.y * ev) * C_INV_SQRT_H;
                msg.z = (vv.z * m2.z + m3.z * ev) * C_INV_SQRT_H;
                msg.w = (vv.w * m2.w + m3.w * ev) * C_INV_SQRT_H;
                red4(dvp + c * 128 + c4, msg);
            }
        }
    }
}

// ---------------------------------------------------------------------------
__global__ void dotnorm_kernel() {
    int i = blockIdx.x * blockDim.x + threadIdx.x;
    if (i >= NN * HD) return;
    int n = i >> 7;
    int h = i & 127;
    const float* vp = g_vproj + (size_t)n * 768;
    float d = 0.f, s = 0.f;
#pragma unroll
    for (int c = 0; c < 3; c++) {
        float v1 = vp[c * 256 + h];
        float v2 = vp[c * 256 + 128 + h];
        d += v1 * v2;
        s += v2 * v2;
    }
    float xn = g_dx[i] * C_INV_SQRT_2;
    g_vecdot[i] = d * C_INV_SQRT_H;
    g_cat[(size_t)n * 256 + h] = f2tf32(xn);
    g_cat[(size_t)n * 256 + 128 + h] = f2tf32(sqrtf(s + 1e-8f));
}

// ---------------------------------------------------------------------------
__global__ void finalize_kernel(float* __restrict__ out) {
    int i = blockIdx.x * blockDim.x + threadIdx.x;
    if (i >= NN * HD) return;
    int n = i >> 7;
    int h = i & 127;
    const float* hb = g_hbuf + (size_t)n * 384;
    float xv1 = hb[h];
    float xv2 = hb[128 + h];
    float xv3 = hb[256 + h];
    float* out_vec = out;
    float* out_x = out + (size_t)NN * 3 * HD;
    float xn = g_dx[i] * C_INV_SQRT_2;
    out_x[i] = xn + (xv1 + xv2 * g_vecdot[i]) * C_INV_SQRT_2;
#pragma unroll
    for (int c = 0; c < 3; c++) {
        size_t idx = (size_t)n * 384 + c * HD + h;
        out_vec[idx] = g_dvec[idx] + xv3 * g_vproj[(size_t)n * 768 + c * 256 + h];
    }
}

// ---------------------------------------------------------------------------
extern "C" void kernel_launch(void* const* d_in, const int* in_sizes, int n_in,
                              void* d_out, int out_size) {
    const float* x    = (const float*)d_in[0];
    const float* vec  = (const float*)d_in[1];
    const int*   ei   = (const int*)d_in[2];
    const float* ee   = (const float*)d_in[3];
    const float* evec = (const float*)d_in[4];
    const float* ln_g = (const float*)d_in[5];
    const float* ln_b = (const float*)d_in[6];
    const float* W1   = (const float*)d_in[7];
    const float* b1   = (const float*)d_in[8];
    const float* W2   = (const float*)d_in[9];
    const float* b2   = (const float*)d_in[10];
    const float* Wr   = (const float*)d_in[11];
    const float* br   = (const float*)d_in[12];
    const float* Wv   = (const float*)d_in[13];
    const float* Wu1  = (const float*)d_in[14];
    const float* bu1  = (const float*)d_in[15];
    const float* Wu2  = (const float*)d_in[16];
    const float* bu2  = (const float*)d_in[17];

    float* out = (float*)d_out;

    float* xln = nullptr;     cudaGetSymbolAddress((void**)&xln, g_xln);
    float* t1 = nullptr;      cudaGetSymbolAddress((void**)&t1, g_t1);
    float* vproj = nullptr;   cudaGetSymbolAddress((void**)&vproj, g_vproj);
    float* cat = nullptr;     cudaGetSymbolAddress((void**)&cat, g_cat);
    float* u = nullptr;       cudaGetSymbolAddress((void**)&u, g_u);
    float* hbuf = nullptr;    cudaGetSymbolAddress((void**)&hbuf, g_hbuf);
    float* xh = nullptr;      cudaGetSymbolAddress((void**)&xh, g_xh);
    float* w1t = nullptr;     cudaGetSymbolAddress((void**)&w1t, g_W1t);
    float* w2t = nullptr;     cudaGetSymbolAddress((void**)&w2t, g_W2t);
    float* wu1t = nullptr;    cudaGetSymbolAddress((void**)&wu1t, g_Wu1t);
    float* wu2t = nullptr;    cudaGetSymbolAddress((void**)&wu2t, g_Wu2t);

    const int SMEM_NODE  = (2 * 128 * ASW + 2 * 32 * 136) * 4;  // 71680
    const int SMEM_EDGE  = (64 * 68 + 64 * 264) * 4;            // 84992 (max path)
    const int SMEM_VPROJ = (128 * 132 + 2 * 32 * 136) * 4;      // 102400

    cudaFuncSetAttribute((const void*)gemm_tc<0, 0>,
                         cudaFuncAttributeMaxDynamicSharedMemorySize, SMEM_NODE);
    cudaFuncSetAttribute((const void*)gemm_tc<1, 1>,
                         cudaFuncAttributeMaxDynamicSharedMemorySize, SMEM_NODE);
    cudaFuncSetAttribute((const void*)edge_gemm_all,
                         cudaFuncAttributeMaxDynamicSharedMemorySize, SMEM_EDGE);
    cudaFuncSetAttribute((const void*)gemm_vproj,
                         cudaFuncAttributeMaxDynamicSharedMemorySize, SMEM_VPROJ);

    // 1. prep: LN + accumulator init (dx=x, dvec=vec) + weight rounding
    prep_kernel<<<4096 + 4096, 256>>>(x, vec, ln_g, ln_b,
                                      W1, W2, Wr, Wv, Wu1, Wu2);

    // 2. t1 = rna(scaled_silu(xln @ W1 + b1))
    gemm_tc<1, 1><<<dim3(1, NN / 128), 256, SMEM_NODE>>>(xln, w1t, b1, t1,
                                                         NN, 128, 128);
    // 3. xh = t1 @ W2 + b2
    gemm_tc<0, 0><<<dim3(3, NN / 128), 256, SMEM_NODE>>>(t1, w2t, b2, xh,
                                                         NN, 384, 128);

    // 4. merged edge kernel (segregated dx then dvec blocks; ee evict-first)
    edge_gemm_all<<<4096 + 8192, 256, SMEM_EDGE>>>(ee, br, ei, vec, evec);

    // 5. vproj = rna(vec_new) @ Wv
    gemm_vproj<<<dim3(2, (3 * NN) / 128), 256, SMEM_VPROJ>>>(vproj);

    // 6. x_new + vec_dot / vec2_norm / cat
    dotnorm_kernel<<<(NN * HD) / 256, 256>>>();

    // 7. u = rna(scaled_silu(cat @ Wu1 + bu1))
    gemm_tc<1, 1><<<dim3(1, NN / 128), 256, SMEM_NODE>>>(cat, wu1t, bu1, u,
                                                         NN, 128, 256);
    // 8. hbuf = u @ Wu2 + bu2
    gemm_tc<0, 0><<<dim3(3, NN / 128), 256, SMEM_NODE>>>(u, wu2t, bu2, hbuf,
                                                         NN, 384, 128);

    // 9. finalize
    finalize_kernel<<<(NN * HD) / 256, 256>>>(out);
}

// round 16
// speedup vs baseline: 1.0945x; 1.0056x over previous
#include <cuda_runtime.h>
#include <math.h>
#include <stdint.h>

#define NN 32768
#define NE 524288
#define HD 128
#define ASW 36

__device__ __forceinline__ float ssilu(float v) {
    return v / ((1.0f + __expf(-v)) * 0.6f);
}
__device__ __forceinline__ float f2tf32(float x) {
    float r;
    asm("cvt.rna.tf32.f32 %0, %1;" : "=f"(r) : "f"(x));
    return r;
}
__device__ __forceinline__ float4 rnd4(float4 v) {
    v.x = f2tf32(v.x); v.y = f2tf32(v.y);
    v.z = f2tf32(v.z); v.w = f2tf32(v.w);
    return v;
}

// scratch ------------------------------------------------------------------
static __device__ float g_xln[NN * HD];
static __device__ float g_xh[NN * 3 * HD];
static __device__ float g_dx[NN * HD];        // init = x, accumulates dx
static __device__ float g_dvec[NN * 3 * HD];  // init = vec, accumulates dvec
static __device__ float g_vproj[NN * 3 * 2 * HD];
static __device__ float g_vecdot[NN * HD];
static __device__ float g_cat[NN * 2 * HD];
static __device__ float g_hbuf[NN * 3 * HD];
static __device__ float g_W1t[128 * 128];
static __device__ float g_W2t[128 * 384];
static __device__ float g_Wrt[64 * 384];
static __device__ float g_Wvt[128 * 256];
static __device__ float g_Wu1t[256 * 128];
static __device__ float g_Wu2t[128 * 384];

__constant__ float C_INV_SQRT_3 = 0.57735026918962576451f;
__constant__ float C_INV_SQRT_H = 0.08838834764831844055f;
__constant__ float C_INV_SQRT_2 = 0.70710678118654752440f;

// ---------------------------------------------------------------------------
__device__ __forceinline__ void cp16(float* s, const float* g) {
    uint32_t sa = (uint32_t)__cvta_generic_to_shared(s);
    asm volatile("cp.async.cg.shared.global [%0], [%1], 16;"
                 :: "r"(sa), "l"(g) : "memory");
}
__device__ __forceinline__ void mma8(float c[4], const uint32_t a[4],
                                     uint32_t b0, uint32_t b1) {
    asm volatile(
        "mma.sync.aligned.m16n8k8.row.col.f32.tf32.tf32.f32 "
        "{%0,%1,%2,%3}, {%4,%5,%6,%7}, {%8,%9}, {%0,%1,%2,%3};"
        : "+f"(c[0]), "+f"(c[1]), "+f"(c[2]), "+f"(c[3])
        : "r"(a[0]), "r"(a[1]), "r"(a[2]), "r"(a[3]), "r"(b0), "r"(b1));
}
__device__ __forceinline__ void red4(float* addr, float4 v) {
    asm volatile("red.global.add.v4.f32 [%0], {%1, %2, %3, %4};"
                 :: "l"(addr), "f"(v.x), "f"(v.y), "f"(v.z), "f"(v.w)
                 : "memory");
}
// evict-first streaming load of a float4 (for stream-once data like ee)
__device__ __forceinline__ float4 ld_cs4(const float* p) {
    float4 v;
    asm volatile("ld.global.cs.v4.f32 {%0,%1,%2,%3}, [%4];"
                 : "=f"(v.x), "=f"(v.y), "=f"(v.z), "=f"(v.w) : "l"(p));
    return v;
}

// ---------------------------------------------------------------------------
// prep_kernel: blocks [0,4096) LayerNorm; rest: dx=x, dvec=vec, weight round.
// ---------------------------------------------------------------------------
__global__ void prep_kernel(const float* __restrict__ x,
                            const float* __restrict__ vec,
                            const float* __restrict__ lng,
                            const float* __restrict__ lnb,
                            const float* __restrict__ W1,
                            const float* __restrict__ W2,
                            const float* __restrict__ Wr,
                            const float* __restrict__ Wv,
                            const float* __restrict__ Wu1,
                            const float* __restrict__ Wu2) {
    int blk = blockIdx.x;
    int tid = threadIdx.x;
    if (blk < 4096) {
        int row = blk * 8 + (tid >> 5);
        int lane = tid & 31;
        float4 v = *(const float4*)(x + (size_t)row * HD + lane * 4);
        float s = v.x + v.y + v.z + v.w;
        float s2 = v.x * v.x + v.y * v.y + v.z * v.z + v.w * v.w;
#pragma unroll
        for (int o = 16; o > 0; o >>= 1) {
            s += __shfl_xor_sync(0xffffffffu, s, o);
            s2 += __shfl_xor_sync(0xffffffffu, s2, o);
        }
        float mu = s * (1.0f / HD);
        float var = s2 * (1.0f / HD) - mu * mu;
        float inv = rsqrtf(var + 1e-5f);
        float4 gg = *(const float4*)(lng + lane * 4);
        float4 bb = *(const float4*)(lnb + lane * 4);
        float4 o4;
        o4.x = f2tf32((v.x - mu) * inv * gg.x + bb.x);
        o4.y = f2tf32((v.y - mu) * inv * gg.y + bb.y);
        o4.z = f2tf32((v.z - mu) * inv * gg.z + bb.z);
        o4.w = f2tf32((v.w - mu) * inv * gg.w + bb.w);
        *(float4*)(g_xln + (size_t)row * HD + lane * 4) = o4;
        return;
    }
    const int DX4 = NN * HD / 4;
    const int DV4 = NN * 3 * HD / 4;
    const int s1 = 128 * 128 / 4, s2 = 128 * 384 / 4, s3 = 64 * 384 / 4;
    const int s4 = 128 * 256 / 4, s5 = 256 * 128 / 4, s6 = 128 * 384 / 4;
    const int total = DX4 + DV4 + s1 + s2 + s3 + s4 + s5 + s6;
    int base = (blk - 4096) * 256 + tid;
    int stride = (gridDim.x - 4096) * 256;
    for (int i = base; i < total; i += stride) {
        int j = i;
        if (j < DX4) { ((float4*)g_dx)[j] = ((const float4*)x)[j]; continue; }
        j -= DX4;
        if (j < DV4) { ((float4*)g_dvec)[j] = ((const float4*)vec)[j]; continue; }
        j -= DV4;
        if (j < s1) { ((float4*)g_W1t)[j] = rnd4(((const float4*)W1)[j]); continue; }
        j -= s1;
        if (j < s2) { ((float4*)g_W2t)[j] = rnd4(((const float4*)W2)[j]); continue; }
        j -= s2;
        if (j < s3) { ((float4*)g_Wrt)[j] = rnd4(((const float4*)Wr)[j]); continue; }
        j -= s3;
        if (j < s4) { ((float4*)g_Wvt)[j] = rnd4(((const float4*)Wv)[j]); continue; }
        j -= s4;
        if (j < s5) { ((float4*)g_Wu1t)[j] = rnd4(((const float4*)Wu1)[j]); continue; }
        j -= s5;
        ((float4*)g_Wu2t)[j] = rnd4(((const float4*)Wu2)[j]);
    }
}

// ---------------------------------------------------------------------------
// Double-buffered tf32 MMA mainloop (inputs pre-rounded).
// ---------------------------------------------------------------------------
template <int BM, int BN>
__device__ __forceinline__ void mma_loop(
    const float* __restrict__ A, int lda,
    const float* __restrict__ B, int ldb, int K,
    float* sm, float acc[2][8][4]) {
    const int BSW = BN + 8;
    const int ABUF = BM * ASW;
    const int BBUF = 32 * BSW;
    float* As = sm;
    float* Bs = sm + 2 * ABUF;
    int tid = threadIdx.x;
    int wid = tid >> 5, lane = tid & 31;
    int g = lane >> 2, t = lane & 3;
    const int WN = BN / 64;
    int wm = wid / WN, wn = wid % WN;
    int mbase = wm * 32;

    {
#pragma unroll
        for (int i = 0; i < BM / 32; i++) {
            int f = tid + i * 256;
            int row = f >> 3, c4 = (f & 7) * 4;
            cp16(As + row * ASW + c4, A + (size_t)row * lda + c4);
        }
#pragma unroll
        for (int i = 0; i < BN / 32; i++) {
            int f = tid + i * 256;
            int row = f / (BN / 4), c4 = (f % (BN / 4)) * 4;
            cp16(Bs + row * BSW + c4, B + (size_t)row * ldb + c4);
        }
        asm volatile("cp.async.commit_group;" ::: "memory");
    }

    int nk = K >> 5;
    for (int kc = 0; kc < nk; kc++) {
        if (kc + 1 < nk) {
            int k0 = (kc + 1) * 32;
            float* as = As + ((kc + 1) & 1) * ABUF;
            float* bs = Bs + ((kc + 1) & 1) * BBUF;
#pragma unroll
            for (int i = 0; i < BM / 32; i++) {
                int f = tid + i * 256;
                int row = f >> 3, c4 = (f & 7) * 4;
                cp16(as + row * ASW + c4, A + (size_t)row * lda + k0 + c4);
            }
#pragma unroll
            for (int i = 0; i < BN / 32; i++) {
                int f = tid + i * 256;
                int row = f / (BN / 4), c4 = (f % (BN / 4)) * 4;
                cp16(bs + row * BSW + c4, B + (size_t)(k0 + row) * ldb + c4);
            }
            asm volatile("cp.async.commit_group;" ::: "memory");
            asm volatile("cp.async.wait_group 1;" ::: "memory");
        } else {
            asm volatile("cp.async.wait_group 0;" ::: "memory");
        }
        __syncthreads();
        const float* as = As + (kc & 1) * ABUF;
        const float* bs = Bs + (kc & 1) * BBUF;
#pragma unroll
        for (int ks = 0; ks < 4; ks++) {
            int kk = ks * 8;
            uint32_t af[2][4];
#pragma unroll
            for (int mt = 0; mt < 2; mt++) {
                int r0 = mbase + mt * 16;
                af[mt][0] = __float_as_uint(as[(r0 + g) * ASW + kk + t]);
                af[mt][1] = __float_as_uint(as[(r0 + g + 8) * ASW + kk + t]);
                af[mt][2] = __float_as_uint(as[(r0 + g) * ASW + kk + t + 4]);
                af[mt][3] = __float_as_uint(as[(r0 + g + 8) * ASW + kk + t + 4]);
            }
#pragma unroll
            for (int nt = 0; nt < 8; nt++) {
                int cb = wn * 64 + nt * 8;
                uint32_t b0 = __float_as_uint(bs[(kk + t) * BSW + cb + g]);
                uint32_t b1 = __float_as_uint(bs[(kk + t + 4) * BSW + cb + g]);
#pragma unroll
                for (int mt = 0; mt < 2; mt++) mma8(acc[mt][nt], af[mt], b0, b1);
            }
        }
        __syncthreads();
    }
}

// edge MMA compute over fully-resident K=64 tiles -----------------------------
template <int BM, int BN>
__device__ __forceinline__ void edge_mma_compute(const float* As,
                                                 const float* Bs,
                                                 float acc[2][8][4]) {
    const int ESW = 68, BSW = BN + 8;
    int tid = threadIdx.x;
    int wid = tid >> 5, lane = tid & 31;
    int g = lane >> 2, t = lane & 3;
    const int WN = BN / 64;
    int wm = wid / WN, wn = wid % WN;
    int mbase = wm * 32;
#pragma unroll
    for (int ks = 0; ks < 8; ks++) {
        int kk = ks * 8;
        uint32_t af[2][4];
#pragma unroll
        for (int mt = 0; mt < 2; mt++) {
            int r0 = mbase + mt * 16;
            af[mt][0] = __float_as_uint(As[(r0 + g) * ESW + kk + t]);
            af[mt][1] = __float_as_uint(As[(r0 + g + 8) * ESW + kk + t]);
            af[mt][2] = __float_as_uint(As[(r0 + g) * ESW + kk + t + 4]);
            af[mt][3] = __float_as_uint(As[(r0 + g + 8) * ESW + kk + t + 4]);
        }
#pragma unroll
        for (int nt = 0; nt < 8; nt++) {
            int cb = wn * 64 + nt * 8;
            uint32_t b0 = __float_as_uint(Bs[(kk + t) * BSW + cb + g]);
            uint32_t b1 = __float_as_uint(Bs[(kk + t + 4) * BSW + cb + g]);
#pragma unroll
            for (int mt = 0; mt < 2; mt++) mma8(acc[mt][nt], af[mt], b0, b1);
        }
    }
}

#define ACC_INIT(acc)                                   \
    _Pragma("unroll") for (int i = 0; i < 2; i++)       \
    _Pragma("unroll") for (int j = 0; j < 8; j++)       \
    _Pragma("unroll") for (int k = 0; k < 4; k++) acc[i][j][k] = 0.f;

// ---------------------------------------------------------------------------
// Fused MLP: t = rna(ssilu(A@Wa + ba)) kept in SMEM, then C = t@Wb + bb.
// A: [NN,KA], Wa: [KA,128], Wb: [128,384], C: [NN,384]. One 128-row block each.
// SMEM: [0, 17920) phase-1 A+B (reused as t1s 128x132 after mainloop),
//       [17920, 26624) phase-2 B double buffer (2 x 32 x 136).
// ---------------------------------------------------------------------------
template <int KA>
__global__ void __launch_bounds__(256, 2)
fused_mlp(const float* __restrict__ A, const float* __restrict__ Wa,
          const float* __restrict__ ba, const float* __restrict__ Wb,
          const float* __restrict__ bb, float* __restrict__ C) {
    extern __shared__ float sm[];
    float acc[2][8][4];
    ACC_INIT(acc)
    int bm = blockIdx.x * 128;
    mma_loop<128, 128>(A + (size_t)bm * KA, KA, Wa, 128, KA, sm, acc);

    int tid = threadIdx.x;
    int wid = tid >> 5, lane = tid & 31;
    int g = lane >> 2, t = lane & 3;
    int wm = wid >> 1, wn = wid & 1;

    // phase-1 epilogue -> t1s (overlaps dead phase-1 staging buffers)
    float* t1s = sm;   // 128 x 132
#pragma unroll
    for (int mt = 0; mt < 2; mt++) {
#pragma unroll
        for (int h = 0; h < 2; h++) {
            int row = wm * 32 + mt * 16 + g + h * 8;
#pragma unroll
            for (int nt = 0; nt < 8; nt++) {
                int c = wn * 64 + nt * 8 + 2 * t;
                float2 bbv = *(const float2*)(ba + c);
                t1s[row * 132 + c]     = f2tf32(ssilu(acc[mt][nt][2 * h + 0] + bbv.x));
                t1s[row * 132 + c + 1] = f2tf32(ssilu(acc[mt][nt][2 * h + 1] + bbv.y));
            }
        }
    }
    __syncthreads();

    // phase 2: C[:, nc*128 : nc*128+128] = t1s @ Wb[:, nc*128...]
    float* Bs = sm + 17920;
    int mbase = wm * 32;
#pragma unroll 1
    for (int nc = 0; nc < 3; nc++) {
        const float* B = Wb + nc * 128;   // ldb = 384
        ACC_INIT(acc)
        // prefetch chunk 0
#pragma unroll
        for (int i = 0; i < 4; i++) {
            int f = tid + i * 256;
            int row = f >> 5, c4 = (f & 31) * 4;
            cp16(Bs + row * 136 + c4, B + (size_t)row * 384 + c4);
        }
        asm volatile("cp.async.commit_group;" ::: "memory");
        for (int kc = 0; kc < 4; kc++) {
            if (kc < 3) {
                int k0 = (kc + 1) * 32;
                float* bs = Bs + ((kc + 1) & 1) * (32 * 136);
#pragma unroll
                for (int i = 0; i < 4; i++) {
                    int f = tid + i * 256;
                    int row = f >> 5, c4 = (f & 31) * 4;
                    cp16(bs + row * 136 + c4, B + (size_t)(k0 + row) * 384 + c4);
                }
                asm volatile("cp.async.commit_group;" ::: "memory");
                asm volatile("cp.async.wait_group 1;" ::: "memory");
            } else {
                asm volatile("cp.async.wait_group 0;" ::: "memory");
            }
            __syncthreads();
            const float* bs = Bs + (kc & 1) * (32 * 136);
            int kg = kc * 32;
#pragma unroll
            for (int ks = 0; ks < 4; ks++) {
                int kk = kg + ks * 8;
                uint32_t af[2][4];
#pragma unroll
                for (int mt = 0; mt < 2; mt++) {
                    int r0 = mbase + mt * 16;
                    af[mt][0] = __float_as_uint(t1s[(r0 + g) * 132 + kk + t]);
                    af[mt][1] = __float_as_uint(t1s[(r0 + g + 8) * 132 + kk + t]);
                    af[mt][2] = __float_as_uint(t1s[(r0 + g) * 132 + kk + t + 4]);
                    af[mt][3] = __float_as_uint(t1s[(r0 + g + 8) * 132 + kk + t + 4]);
                }
#pragma unroll
                for (int nt = 0; nt < 8; nt++) {
                    int cb = wn * 64 + nt * 8;
                    uint32_t b0 = __float_as_uint(bs[(ks * 8 + t) * 136 + cb + g]);
                    uint32_t b1 = __float_as_uint(bs[(ks * 8 + t + 4) * 136 + cb + g]);
#pragma unroll
                    for (int mt = 0; mt < 2; mt++) mma8(acc[mt][nt], af[mt], b0, b1);
                }
            }
            __syncthreads();
        }
        // store this N-chunk
#pragma unroll
        for (int mt = 0; mt < 2; mt++) {
#pragma unroll
            for (int h = 0; h < 2; h++) {
                int r = bm + wm * 32 + mt * 16 + g + h * 8;
#pragma unroll
                for (int nt = 0; nt < 8; nt++) {
                    int c = wn * 64 + nt * 8 + 2 * t;
                    float2 bbv = *(const float2*)(bb + nc * 128 + c);
                    float2 o;
                    o.x = acc[mt][nt][2 * h + 0] + bbv.x;
                    o.y = acc[mt][nt][2 * h + 1] + bbv.y;
                    *(float2*)(C + (size_t)r * 384 + nc * 128 + c) = o;
                }
            }
        }
    }
}

// ---------------------------------------------------------------------------
// vproj GEMM: g_vproj[3N,256] = rna(g_dvec)[3N,128] @ Wvt[128,256].
// ---------------------------------------------------------------------------
__global__ void __launch_bounds__(256, 2)
gemm_vproj(float* __restrict__ C) {
    extern __shared__ float sm[];
    float* As = sm;                 // 128 x 132
    float* Bs = sm + 128 * 132;     // 2 x 32 x 136
    int tid = threadIdx.x;
    int bm = blockIdx.y * 128;
    int bn = blockIdx.x * 128;
    const float* B = g_Wvt + bn;

#pragma unroll
    for (int i = 0; i < 4; i++) {
        int f = tid + i * 256;
        int row = f >> 5, c4 = (f & 31) * 4;
        cp16(Bs + row * 136 + c4, B + (size_t)row * 256 + c4);
    }
    asm volatile("cp.async.commit_group;" ::: "memory");

#pragma unroll
    for (int i = 0; i < 16; i++) {
        int f = tid + i * 256;
        int row = f >> 5, c4 = (f & 31) * 4;
        float4 v = rnd4(*(const float4*)(g_dvec + (size_t)(bm + row) * 128 + c4));
        *(float4*)(As + row * 132 + c4) = v;
    }

    int wid = tid >> 5, lane = tid & 31;
    int g = lane >> 2, t = lane & 3;
    int wm = wid >> 1, wn = wid & 1;
    int mbase = wm * 32;
    float acc[2][8][4];
    ACC_INIT(acc)

    for (int kc = 0; kc < 4; kc++) {
        if (kc < 3) {
            int k0 = (kc + 1) * 32;
            float* bs = Bs + ((kc + 1) & 1) * (32 * 136);
#pragma unroll
            for (int i = 0; i < 4; i++) {
                int f = tid + i * 256;
                int row = f >> 5, c4 = (f & 31) * 4;
                cp16(bs + row * 136 + c4, B + (size_t)(k0 + row) * 256 + c4);
            }
            asm volatile("cp.async.commit_group;" ::: "memory");
            asm volatile("cp.async.wait_group 1;" ::: "memory");
        } else {
            asm volatile("cp.async.wait_group 0;" ::: "memory");
        }
        __syncthreads();
        const float* bs = Bs + (kc & 1) * (32 * 136);
        int kg = kc * 32;
#pragma unroll
        for (int ks = 0; ks < 4; ks++) {
            int kk = ks * 8;
            uint32_t af[2][4];
#pragma unroll
            for (int mt = 0; mt < 2; mt++) {
                int r0 = mbase + mt * 16;
                af[mt][0] = __float_as_uint(As[(r0 + g) * 132 + kg + kk + t]);
                af[mt][1] = __float_as_uint(As[(r0 + g + 8) * 132 + kg + kk + t]);
                af[mt][2] = __float_as_uint(As[(r0 + g) * 132 + kg + kk + t + 4]);
                af[mt][3] = __float_as_uint(As[(r0 + g + 8) * 132 + kg + kk + t + 4]);
            }
#pragma unroll
            for (int nt = 0; nt < 8; nt++) {
                int cb = wn * 64 + nt * 8;
                uint32_t b0 = __float_as_uint(bs[(kk + t) * 136 + cb + g]);
                uint32_t b1 = __float_as_uint(bs[(kk + t + 4) * 136 + cb + g]);
#pragma unroll
                for (int mt = 0; mt < 2; mt++) mma8(acc[mt][nt], af[mt], b0, b1);
            }
        }
        __syncthreads();
    }

#pragma unroll
    for (int mt = 0; mt < 2; mt++) {
#pragma unroll
        for (int h = 0; h < 2; h++) {
            int r = bm + wm * 32 + mt * 16 + g + h * 8;
#pragma unroll
            for (int nt = 0; nt < 8; nt++) {
                int c = bn + wn * 64 + nt * 8 + 2 * t;
                float2 o = {acc[mt][nt][2 * h + 0], acc[mt][nt][2 * h + 1]};
                *(float2*)(C + (size_t)r * 256 + c) = o;
            }
        }
    }
}

// ---------------------------------------------------------------------------
// Merged edge kernel (segregated): blocks [0,4096) dx; [4096,12288) dvec.
// ee staged with evict-first loads; ei/evec also streaming.
// ---------------------------------------------------------------------------
__global__ void __launch_bounds__(256, 2)
edge_gemm_all(const float* __restrict__ ee, const float* __restrict__ br,
              const int* __restrict__ ei, const float* __restrict__ vec,
              const float* __restrict__ evec) {
    const int ESW = 68;
    extern __shared__ float sm[];
    __shared__ int s_src[128];
    __shared__ int s_dst[128];
    __shared__ float s_ev[3][64];
    int tid = threadIdx.x;

    if (blockIdx.x < 4096) {
        // ----------------- dx path: 128 edges, BN=128 -----------------
        const int BSW = 136;
        float* As = sm;
        float* Bs = sm + 128 * ESW;
        int bm = blockIdx.x * 128;

#pragma unroll
        for (int i = 0; i < 8; i++) {
            int f = tid + i * 256;
            int row = f >> 5, c4 = (f & 31) * 4;
            cp16(Bs + row * BSW + c4, g_Wrt + (size_t)row * 384 + c4);
        }
        asm volatile("cp.async.commit_group;" ::: "memory");

        if (tid < 128) {
            s_src[tid] = __ldcs(ei + bm + tid);
            s_dst[tid] = __ldcs(ei + NE + bm + tid);
        }

#pragma unroll
        for (int i = 0; i < 8; i++) {
            int f = tid + i * 256;
            int row = f >> 4, c4 = (f & 15) * 4;
            float4 v = rnd4(ld_cs4(ee + (size_t)(bm + row) * 64 + c4));
            *(float4*)(As + row * ESW + c4) = v;
        }
        asm volatile("cp.async.wait_group 0;" ::: "memory");
        __syncthreads();

        float acc[2][8][4];
        ACC_INIT(acc)
        edge_mma_compute<128, 128>(As, Bs, acc);
        __syncthreads();

        float* sbuf = sm;   // 128 x 132
        int wid = tid >> 5, lane = tid & 31;
        int g = lane >> 2, t = lane & 3;
        int wm = wid >> 1, wn = wid & 1;
#pragma unroll
        for (int mt = 0; mt < 2; mt++) {
#pragma unroll
            for (int h = 0; h < 2; h++) {
                int row = wm * 32 + mt * 16 + g + h * 8;
#pragma unroll
                for (int nt = 0; nt < 8; nt++) {
                    int col = wn * 64 + nt * 8 + 2 * t;
                    float2 bb = *(const float2*)(br + col);
                    sbuf[row * 132 + col]     = acc[mt][nt][2 * h + 0] + bb.x;
                    sbuf[row * 132 + col + 1] = acc[mt][nt][2 * h + 1] + bb.y;
                }
            }
        }
        __syncthreads();
#pragma unroll
        for (int i = 0; i < 16; i++) {
            int f = tid + i * 256;
            int e = f >> 5;
            int c4 = (f & 31) * 4;
            int src = s_src[e], dst = s_dst[e];
            float4 m = *(float4*)(sbuf + e * 132 + c4);
            float4 x1 = *(const float4*)(g_xh + (size_t)src * 384 + c4);
            m.x *= x1.x; m.y *= x1.y; m.z *= x1.z; m.w *= x1.w;
            red4(g_dx + (size_t)dst * HD + c4, m);
        }
    } else {
        // ----------------- dvec path: 64 edges, BN=256 -----------------
        const int BSW = 264;
        float* As = sm;
        float* Bs = sm + 64 * ESW;
        int bm = (blockIdx.x - 4096) * 64;

#pragma unroll
        for (int i = 0; i < 16; i++) {
            int f = tid + i * 256;
            int row = f >> 6, c4 = (f & 63) * 4;
            cp16(Bs + row * BSW + c4, g_Wrt + 128 + (size_t)row * 384 + c4);
        }
        asm volatile("cp.async.commit_group;" ::: "memory");

        if (tid < 64) {
            s_src[tid] = __ldcs(ei + bm + tid);
            s_dst[tid] = __ldcs(ei + NE + bm + tid);
        }
        if (tid < 192) {
            int e = tid & 63;
            int c = tid >> 6;
            s_ev[c][e] = __ldcs(evec + (size_t)(bm + e) * 3 + c);
        }

#pragma unroll
        for (int i = 0; i < 4; i++) {
            int f = tid + i * 256;
            int row = f >> 4, c4 = (f & 15) * 4;
            float4 v = rnd4(ld_cs4(ee + (size_t)(bm + row) * 64 + c4));
            *(float4*)(As + row * ESW + c4) = v;
        }
        asm volatile("cp.async.wait_group 0;" ::: "memory");
        __syncthreads();

        float acc[2][8][4];
        ACC_INIT(acc)
        edge_mma_compute<64, 256>(As, Bs, acc);
        __syncthreads();

        float* sbuf = sm;   // 64 x 260
        int wid = tid >> 5, lane = tid & 31;
        int g = lane >> 2, t = lane & 3;
        int wm = wid >> 2, wn = wid & 3;
#pragma unroll
        for (int mt = 0; mt < 2; mt++) {
#pragma unroll
            for (int h = 0; h < 2; h++) {
                int row = wm * 32 + mt * 16 + g + h * 8;
#pragma unroll
                for (int nt = 0; nt < 8; nt++) {
                    int col = wn * 64 + nt * 8 + 2 * t;
                    float2 bb = *(const float2*)(br + 128 + col);
                    sbuf[row * 260 + col]     = acc[mt][nt][2 * h + 0] + bb.x;
                    sbuf[row * 260 + col + 1] = acc[mt][nt][2 * h + 1] + bb.y;
                }
            }
        }
        __syncthreads();
#pragma unroll
        for (int i = 0; i < 8; i++) {
            int f = tid + i * 256;
            int e = f >> 5;
            int c4 = (f & 31) * 4;
            int src = s_src[e], dst = s_dst[e];
            float ev0 = s_ev[0][e], ev1 = s_ev[1][e], ev2 = s_ev[2][e];
            float4 r2 = *(float4*)(sbuf + e * 260 + c4);
            float4 r3 = *(float4*)(sbuf + e * 260 + 128 + c4);
            const float* xhp = g_xh + (size_t)src * 384;
            float4 x2 = *(const float4*)(xhp + 128 + c4);
            float4 x3 = *(const float4*)(xhp + 256 + c4);
            float4 m2, m3;
            m2.x = r2.x * x2.x * C_INV_SQRT_3; m2.y = r2.y * x2.y * C_INV_SQRT_3;
            m2.z = r2.z * x2.z * C_INV_SQRT_3; m2.w = r2.w * x2.w * C_INV_SQRT_3;
            m3.x = r3.x * x3.x; m3.y = r3.y * x3.y;
            m3.z = r3.z * x3.z; m3.w = r3.w * x3.w;
            const float* vp = vec + (size_t)src * 384;
            float* dvp = g_dvec + (size_t)dst * 384;
#pragma unroll
            for (int c = 0; c < 3; c++) {
                float ev = (c == 0) ? ev0 : ((c == 1) ? ev1 : ev2);
                float4 vv = *(const float4*)(vp + c * 128 + c4);
                float4 msg;
                msg.x = (vv.x * m2.x + m3.x * ev) * C_INV_SQRT_H;
                msg.y = (vv.y * m2.y + m3.y * ev) * C_INV_SQRT_H;
                msg.z = (vv.z * m2.z + m3.z * ev) * C_INV_SQRT_H;
                msg.w = (vv.w * m2.w + m3.w * ev) * C_INV_SQRT_H;
                red4(dvp + c * 128 + c4, msg);
            }
        }
    }
}

// ---------------------------------------------------------------------------
__global__ void dotnorm_kernel() {
    int i = blockIdx.x * blockDim.x + threadIdx.x;
    if (i >= NN * HD) return;
    int n = i >> 7;
    int h = i & 127;
    const float* vp = g_vproj + (size_t)n * 768;
    float d = 0.f, s = 0.f;
#pragma unroll
    for (int c = 0; c < 3; c++) {
        float v1 = vp[c * 256 + h];
        float v2 = vp[c * 256 + 128 + h];
        d += v1 * v2;
        s += v2 * v2;
    }
    float xn = g_dx[i] * C_INV_SQRT_2;
    g_vecdot[i] = d * C_INV_SQRT_H;
    g_cat[(size_t)n * 256 + h] = f2tf32(xn);
    g_cat[(size_t)n * 256 + 128 + h] = f2tf32(sqrtf(s + 1e-8f));
}

// ---------------------------------------------------------------------------
__global__ void finalize_kernel(float* __restrict__ out) {
    int i = blockIdx.x * blockDim.x + threadIdx.x;
    if (i >= NN * HD) return;
    int n = i >> 7;
    int h = i & 127;
    const float* hb = g_hbuf + (size_t)n * 384;
    float xv1 = hb[h];
    float xv2 = hb[128 + h];
    float xv3 = hb[256 + h];
    float* out_vec = out;
    float* out_x = out + (size_t)NN * 3 * HD;
    float xn = g_dx[i] * C_INV_SQRT_2;
    out_x[i] = xn + (xv1 + xv2 * g_vecdot[i]) * C_INV_SQRT_2;
#pragma unroll
    for (int c = 0; c < 3; c++) {
        size_t idx = (size_t)n * 384 + c * HD + h;
        out_vec[idx] = g_dvec[idx] + xv3 * g_vproj[(size_t)n * 768 + c * 256 + h];
    }
}

// ---------------------------------------------------------------------------
extern "C" void kernel_launch(void* const* d_in, const int* in_sizes, int n_in,
                              void* d_out, int out_size) {
    const float* x    = (const float*)d_in[0];
    const float* vec  = (const float*)d_in[1];
    const int*   ei   = (const int*)d_in[2];
    const float* ee   = (const float*)d_in[3];
    const float* evec = (const float*)d_in[4];
    const float* ln_g = (const float*)d_in[5];
    const float* ln_b = (const float*)d_in[6];
    const float* W1   = (const float*)d_in[7];
    const float* b1   = (const float*)d_in[8];
    const float* W2   = (const float*)d_in[9];
    const float* b2   = (const float*)d_in[10];
    const float* Wr   = (const float*)d_in[11];
    const float* br   = (const float*)d_in[12];
    const float* Wv   = (const float*)d_in[13];
    const float* Wu1  = (const float*)d_in[14];
    const float* bu1  = (const float*)d_in[15];
    const float* Wu2  = (const float*)d_in[16];
    const float* bu2  = (const float*)d_in[17];

    float* out = (float*)d_out;

    float* xln = nullptr;     cudaGetSymbolAddress((void**)&xln, g_xln);
    float* vproj = nullptr;   cudaGetSymbolAddress((void**)&vproj, g_vproj);
    float* cat = nullptr;     cudaGetSymbolAddress((void**)&cat, g_cat);
    float* hbuf = nullptr;    cudaGetSymbolAddress((void**)&hbuf, g_hbuf);
    float* xh = nullptr;      cudaGetSymbolAddress((void**)&xh, g_xh);
    float* w1t = nullptr;     cudaGetSymbolAddress((void**)&w1t, g_W1t);
    float* w2t = nullptr;     cudaGetSymbolAddress((void**)&w2t, g_W2t);
    float* wu1t = nullptr;    cudaGetSymbolAddress((void**)&wu1t, g_Wu1t);
    float* wu2t = nullptr;    cudaGetSymbolAddress((void**)&wu2t, g_Wu2t);

    const int SMEM_EDGE  = (64 * 68 + 64 * 264) * 4;            // 84992
    const int SMEM_VPROJ = (128 * 132 + 2 * 32 * 136) * 4;      // 102400
    const int SMEM_FMLP  = (2 * 128 * ASW + 2 * 32 * 136 + 2 * 32 * 136) * 4; // 106496

    cudaFuncSetAttribute((const void*)fused_mlp<128>,
                         cudaFuncAttributeMaxDynamicSharedMemorySize, SMEM_FMLP);
    cudaFuncSetAttribute((const void*)fused_mlp<256>,
                         cudaFuncAttributeMaxDynamicSharedMemorySize, SMEM_FMLP);
    cudaFuncSetAttribute((const void*)edge_gemm_all,
                         cudaFuncAttributeMaxDynamicSharedMemorySize, SMEM_EDGE);
    cudaFuncSetAttribute((const void*)gemm_vproj,
                         cudaFuncAttributeMaxDynamicSharedMemorySize, SMEM_VPROJ);

    // 1. prep: LN + accumulator init (dx=x, dvec=vec) + weight rounding
    prep_kernel<<<4096 + 4096, 256>>>(x, vec, ln_g, ln_b,
                                      W1, W2, Wr, Wv, Wu1, Wu2);

    // 2. fused message MLP: xh = (ssilu(xln@W1+b1)) @ W2 + b2
    fused_mlp<128><<<NN / 128, 256, SMEM_FMLP>>>(xln, w1t, b1, w2t, b2, xh);

    // 3. merged edge kernel
    edge_gemm_all<<<4096 + 8192, 256, SMEM_EDGE>>>(ee, br, ei, vec, evec);

    // 4. vproj = rna(vec_new) @ Wv
    gemm_vproj<<<dim3(2, (3 * NN) / 128), 256, SMEM_VPROJ>>>(vproj);

    // 5. x_new + vec_dot / vec2_norm / cat
    dotnorm_kernel<<<(NN * HD) / 256, 256>>>();

    // 6. fused update MLP: hbuf = (ssilu(cat@Wu1+bu1)) @ Wu2 + bu2
    fused_mlp<256><<<NN / 128, 256, SMEM_FMLP>>>(cat, wu1t, bu1, wu2t, bu2, hbuf);

    // 7. finalize
    finalize_kernel<<<(NN * HD) / 256, 256>>>(out);
}

// round 17
// speedup vs baseline: 1.0975x; 1.0027x over previous
#include <cuda_runtime.h>
#include <math.h>
#include <stdint.h>

#define NN 32768
#define NE 524288
#define HD 128
#define ASW 36

__device__ __forceinline__ float ssilu(float v) {
    return v / ((1.0f + __expf(-v)) * 0.6f);
}
__device__ __forceinline__ float f2tf32(float x) {
    float r;
    asm("cvt.rna.tf32.f32 %0, %1;" : "=f"(r) : "f"(x));
    return r;
}
__device__ __forceinline__ float4 rnd4(float4 v) {
    v.x = f2tf32(v.x); v.y = f2tf32(v.y);
    v.z = f2tf32(v.z); v.w = f2tf32(v.w);
    return v;
}

// scratch ------------------------------------------------------------------
static __device__ float g_xln[NN * HD];
static __device__ float g_xh[NN * 3 * HD];
static __device__ float g_dx[NN * HD];        // init = x, accumulates dx
static __device__ float g_dvec[NN * 3 * HD];  // init = vec, accumulates dvec
static __device__ float g_vproj[NN * 3 * 2 * HD];
static __device__ float g_vecdot[NN * HD];
static __device__ float g_cat[NN * 2 * HD];
static __device__ float g_hbuf[NN * 3 * HD];
static __device__ float g_W1t[128 * 128];
static __device__ float g_W2t[128 * 384];
static __device__ float g_Wrt[64 * 384];
static __device__ float g_Wvt[128 * 256];
static __device__ float g_Wu1t[256 * 128];
static __device__ float g_Wu2t[128 * 384];

__constant__ float C_INV_SQRT_3 = 0.57735026918962576451f;
__constant__ float C_INV_SQRT_H = 0.08838834764831844055f;
__constant__ float C_INV_SQRT_2 = 0.70710678118654752440f;

// ---------------------------------------------------------------------------
__device__ __forceinline__ void cp16(float* s, const float* g) {
    uint32_t sa = (uint32_t)__cvta_generic_to_shared(s);
    asm volatile("cp.async.cg.shared.global [%0], [%1], 16;"
                 :: "r"(sa), "l"(g) : "memory");
}
__device__ __forceinline__ void mma8(float c[4], const uint32_t a[4],
                                     uint32_t b0, uint32_t b1) {
    asm volatile(
        "mma.sync.aligned.m16n8k8.row.col.f32.tf32.tf32.f32 "
        "{%0,%1,%2,%3}, {%4,%5,%6,%7}, {%8,%9}, {%0,%1,%2,%3};"
        : "+f"(c[0]), "+f"(c[1]), "+f"(c[2]), "+f"(c[3])
        : "r"(a[0]), "r"(a[1]), "r"(a[2]), "r"(a[3]), "r"(b0), "r"(b1));
}
__device__ __forceinline__ void red4(float* addr, float4 v) {
    asm volatile("red.global.add.v4.f32 [%0], {%1, %2, %3, %4};"
                 :: "l"(addr), "f"(v.x), "f"(v.y), "f"(v.z), "f"(v.w)
                 : "memory");
}
// evict-first streaming load of a float4 (for stream-once data like ee)
__device__ __forceinline__ float4 ld_cs4(const float* p) {
    float4 v;
    asm volatile("ld.global.cs.v4.f32 {%0,%1,%2,%3}, [%4];"
                 : "=f"(v.x), "=f"(v.y), "=f"(v.z), "=f"(v.w) : "l"(p));
    return v;
}

// ---------------------------------------------------------------------------
// prep_kernel: blocks [0,4096) LayerNorm + g_dx=x; rest: dvec=vec, weights.
// ---------------------------------------------------------------------------
__global__ void prep_kernel(const float* __restrict__ x,
                            const float* __restrict__ vec,
                            const float* __restrict__ lng,
                            const float* __restrict__ lnb,
                            const float* __restrict__ W1,
                            const float* __restrict__ W2,
                            const float* __restrict__ Wr,
                            const float* __restrict__ Wv,
                            const float* __restrict__ Wu1,
                            const float* __restrict__ Wu2) {
    int blk = blockIdx.x;
    int tid = threadIdx.x;
    if (blk < 4096) {
        int row = blk * 8 + (tid >> 5);
        int lane = tid & 31;
        float4 v = *(const float4*)(x + (size_t)row * HD + lane * 4);
        // g_dx accumulator init = x (row already in registers)
        *(float4*)(g_dx + (size_t)row * HD + lane * 4) = v;
        float s = v.x + v.y + v.z + v.w;
        float s2 = v.x * v.x + v.y * v.y + v.z * v.z + v.w * v.w;
#pragma unroll
        for (int o = 16; o > 0; o >>= 1) {
            s += __shfl_xor_sync(0xffffffffu, s, o);
            s2 += __shfl_xor_sync(0xffffffffu, s2, o);
        }
        float mu = s * (1.0f / HD);
        float var = s2 * (1.0f / HD) - mu * mu;
        float inv = rsqrtf(var + 1e-5f);
        float4 gg = *(const float4*)(lng + lane * 4);
        float4 bb = *(const float4*)(lnb + lane * 4);
        float4 o4;
        o4.x = f2tf32((v.x - mu) * inv * gg.x + bb.x);
        o4.y = f2tf32((v.y - mu) * inv * gg.y + bb.y);
        o4.z = f2tf32((v.z - mu) * inv * gg.z + bb.z);
        o4.w = f2tf32((v.w - mu) * inv * gg.w + bb.w);
        *(float4*)(g_xln + (size_t)row * HD + lane * 4) = o4;
        return;
    }
    const int DV4 = NN * 3 * HD / 4;
    const int s1 = 128 * 128 / 4, s2 = 128 * 384 / 4, s3 = 64 * 384 / 4;
    const int s4 = 128 * 256 / 4, s5 = 256 * 128 / 4, s6 = 128 * 384 / 4;
    const int total = DV4 + s1 + s2 + s3 + s4 + s5 + s6;
    int base = (blk - 4096) * 256 + tid;
    int stride = (gridDim.x - 4096) * 256;
    for (int i = base; i < total; i += stride) {
        int j = i;
        if (j < DV4) { ((float4*)g_dvec)[j] = ((const float4*)vec)[j]; continue; }
        j -= DV4;
        if (j < s1) { ((float4*)g_W1t)[j] = rnd4(((const float4*)W1)[j]); continue; }
        j -= s1;
        if (j < s2) { ((float4*)g_W2t)[j] = rnd4(((const float4*)W2)[j]); continue; }
        j -= s2;
        if (j < s3) { ((float4*)g_Wrt)[j] = rnd4(((const float4*)Wr)[j]); continue; }
        j -= s3;
        if (j < s4) { ((float4*)g_Wvt)[j] = rnd4(((const float4*)Wv)[j]); continue; }
        j -= s4;
        if (j < s5) { ((float4*)g_Wu1t)[j] = rnd4(((const float4*)Wu1)[j]); continue; }
        j -= s5;
        ((float4*)g_Wu2t)[j] = rnd4(((const float4*)Wu2)[j]);
    }
}

// ---------------------------------------------------------------------------
// Double-buffered tf32 MMA mainloop (inputs pre-rounded).
// ---------------------------------------------------------------------------
template <int BM, int BN>
__device__ __forceinline__ void mma_loop(
    const float* __restrict__ A, int lda,
    const float* __restrict__ B, int ldb, int K,
    float* sm, float acc[2][8][4]) {
    const int BSW = BN + 8;
    const int ABUF = BM * ASW;
    const int BBUF = 32 * BSW;
    float* As = sm;
    float* Bs = sm + 2 * ABUF;
    int tid = threadIdx.x;
    int wid = tid >> 5, lane = tid & 31;
    int g = lane >> 2, t = lane & 3;
    const int WN = BN / 64;
    int wm = wid / WN, wn = wid % WN;
    int mbase = wm * 32;

    {
#pragma unroll
        for (int i = 0; i < BM / 32; i++) {
            int f = tid + i * 256;
            int row = f >> 3, c4 = (f & 7) * 4;
            cp16(As + row * ASW + c4, A + (size_t)row * lda + c4);
        }
#pragma unroll
        for (int i = 0; i < BN / 32; i++) {
            int f = tid + i * 256;
            int row = f / (BN / 4), c4 = (f % (BN / 4)) * 4;
            cp16(Bs + row * BSW + c4, B + (size_t)row * ldb + c4);
        }
        asm volatile("cp.async.commit_group;" ::: "memory");
    }

    int nk = K >> 5;
    for (int kc = 0; kc < nk; kc++) {
        if (kc + 1 < nk) {
            int k0 = (kc + 1) * 32;
            float* as = As + ((kc + 1) & 1) * ABUF;
            float* bs = Bs + ((kc + 1) & 1) * BBUF;
#pragma unroll
            for (int i = 0; i < BM / 32; i++) {
                int f = tid + i * 256;
                int row = f >> 3, c4 = (f & 7) * 4;
                cp16(as + row * ASW + c4, A + (size_t)row * lda + k0 + c4);
            }
#pragma unroll
            for (int i = 0; i < BN / 32; i++) {
                int f = tid + i * 256;
                int row = f / (BN / 4), c4 = (f % (BN / 4)) * 4;
                cp16(bs + row * BSW + c4, B + (size_t)(k0 + row) * ldb + c4);
            }
            asm volatile("cp.async.commit_group;" ::: "memory");
            asm volatile("cp.async.wait_group 1;" ::: "memory");
        } else {
            asm volatile("cp.async.wait_group 0;" ::: "memory");
        }
        __syncthreads();
        const float* as = As + (kc & 1) * ABUF;
        const float* bs = Bs + (kc & 1) * BBUF;
#pragma unroll
        for (int ks = 0; ks < 4; ks++) {
            int kk = ks * 8;
            uint32_t af[2][4];
#pragma unroll
            for (int mt = 0; mt < 2; mt++) {
                int r0 = mbase + mt * 16;
                af[mt][0] = __float_as_uint(as[(r0 + g) * ASW + kk + t]);
                af[mt][1] = __float_as_uint(as[(r0 + g + 8) * ASW + kk + t]);
                af[mt][2] = __float_as_uint(as[(r0 + g) * ASW + kk + t + 4]);
                af[mt][3] = __float_as_uint(as[(r0 + g + 8) * ASW + kk + t + 4]);
            }
#pragma unroll
            for (int nt = 0; nt < 8; nt++) {
                int cb = wn * 64 + nt * 8;
                uint32_t b0 = __float_as_uint(bs[(kk + t) * BSW + cb + g]);
                uint32_t b1 = __float_as_uint(bs[(kk + t + 4) * BSW + cb + g]);
#pragma unroll
                for (int mt = 0; mt < 2; mt++) mma8(acc[mt][nt], af[mt], b0, b1);
            }
        }
        __syncthreads();
    }
}

// edge MMA compute over fully-resident K=64 tiles -----------------------------
template <int BM, int BN>
__device__ __forceinline__ void edge_mma_compute(const float* As,
                                                 const float* Bs,
                                                 float acc[2][8][4]) {
    const int ESW = 68, BSW = BN + 8;
    int tid = threadIdx.x;
    int wid = tid >> 5, lane = tid & 31;
    int g = lane >> 2, t = lane & 3;
    const int WN = BN / 64;
    int wm = wid / WN, wn = wid % WN;
    int mbase = wm * 32;
#pragma unroll
    for (int ks = 0; ks < 8; ks++) {
        int kk = ks * 8;
        uint32_t af[2][4];
#pragma unroll
        for (int mt = 0; mt < 2; mt++) {
            int r0 = mbase + mt * 16;
            af[mt][0] = __float_as_uint(As[(r0 + g) * ESW + kk + t]);
            af[mt][1] = __float_as_uint(As[(r0 + g + 8) * ESW + kk + t]);
            af[mt][2] = __float_as_uint(As[(r0 + g) * ESW + kk + t + 4]);
            af[mt][3] = __float_as_uint(As[(r0 + g + 8) * ESW + kk + t + 4]);
        }
#pragma unroll
        for (int nt = 0; nt < 8; nt++) {
            int cb = wn * 64 + nt * 8;
            uint32_t b0 = __float_as_uint(Bs[(kk + t) * BSW + cb + g]);
            uint32_t b1 = __float_as_uint(Bs[(kk + t + 4) * BSW + cb + g]);
#pragma unroll
            for (int mt = 0; mt < 2; mt++) mma8(acc[mt][nt], af[mt], b0, b1);
        }
    }
}

#define ACC_INIT(acc)                                   \
    _Pragma("unroll") for (int i = 0; i < 2; i++)       \
    _Pragma("unroll") for (int j = 0; j < 8; j++)       \
    _Pragma("unroll") for (int k = 0; k < 4; k++) acc[i][j][k] = 0.f;

// ---------------------------------------------------------------------------
// Fused MLP: t = rna(ssilu(A@Wa + ba)) kept in SMEM, then C = t@Wb + bb.
// ---------------------------------------------------------------------------
template <int KA>
__global__ void __launch_bounds__(256, 2)
fused_mlp(const float* __restrict__ A, const float* __restrict__ Wa,
          const float* __restrict__ ba, const float* __restrict__ Wb,
          const float* __restrict__ bb, float* __restrict__ C) {
    extern __shared__ float sm[];
    float acc[2][8][4];
    ACC_INIT(acc)
    int bm = blockIdx.x * 128;
    mma_loop<128, 128>(A + (size_t)bm * KA, KA, Wa, 128, KA, sm, acc);

    int tid = threadIdx.x;
    int wid = tid >> 5, lane = tid & 31;
    int g = lane >> 2, t = lane & 3;
    int wm = wid >> 1, wn = wid & 1;

    float* t1s = sm;   // 128 x 132
#pragma unroll
    for (int mt = 0; mt < 2; mt++) {
#pragma unroll
        for (int h = 0; h < 2; h++) {
            int row = wm * 32 + mt * 16 + g + h * 8;
#pragma unroll
            for (int nt = 0; nt < 8; nt++) {
                int c = wn * 64 + nt * 8 + 2 * t;
                float2 bbv = *(const float2*)(ba + c);
                t1s[row * 132 + c]     = f2tf32(ssilu(acc[mt][nt][2 * h + 0] + bbv.x));
                t1s[row * 132 + c + 1] = f2tf32(ssilu(acc[mt][nt][2 * h + 1] + bbv.y));
            }
        }
    }
    __syncthreads();

    float* Bs = sm + 17920;
    int mbase = wm * 32;
#pragma unroll 1
    for (int nc = 0; nc < 3; nc++) {
        const float* B = Wb + nc * 128;   // ldb = 384
        ACC_INIT(acc)
#pragma unroll
        for (int i = 0; i < 4; i++) {
            int f = tid + i * 256;
            int row = f >> 5, c4 = (f & 31) * 4;
            cp16(Bs + row * 136 + c4, B + (size_t)row * 384 + c4);
        }
        asm volatile("cp.async.commit_group;" ::: "memory");
        for (int kc = 0; kc < 4; kc++) {
            if (kc < 3) {
                int k0 = (kc + 1) * 32;
                float* bs = Bs + ((kc + 1) & 1) * (32 * 136);
#pragma unroll
                for (int i = 0; i < 4; i++) {
                    int f = tid + i * 256;
                    int row = f >> 5, c4 = (f & 31) * 4;
                    cp16(bs + row * 136 + c4, B + (size_t)(k0 + row) * 384 + c4);
                }
                asm volatile("cp.async.commit_group;" ::: "memory");
                asm volatile("cp.async.wait_group 1;" ::: "memory");
            } else {
                asm volatile("cp.async.wait_group 0;" ::: "memory");
            }
            __syncthreads();
            const float* bs = Bs + (kc & 1) * (32 * 136);
            int kg = kc * 32;
#pragma unroll
            for (int ks = 0; ks < 4; ks++) {
                int kk = kg + ks * 8;
                uint32_t af[2][4];
#pragma unroll
                for (int mt = 0; mt < 2; mt++) {
                    int r0 = mbase + mt * 16;
                    af[mt][0] = __float_as_uint(t1s[(r0 + g) * 132 + kk + t]);
                    af[mt][1] = __float_as_uint(t1s[(r0 + g + 8) * 132 + kk + t]);
                    af[mt][2] = __float_as_uint(t1s[(r0 + g) * 132 + kk + t + 4]);
                    af[mt][3] = __float_as_uint(t1s[(r0 + g + 8) * 132 + kk + t + 4]);
                }
#pragma unroll
                for (int nt = 0; nt < 8; nt++) {
                    int cb = wn * 64 + nt * 8;
                    uint32_t b0 = __float_as_uint(bs[(ks * 8 + t) * 136 + cb + g]);
                    uint32_t b1 = __float_as_uint(bs[(ks * 8 + t + 4) * 136 + cb + g]);
#pragma unroll
                    for (int mt = 0; mt < 2; mt++) mma8(acc[mt][nt], af[mt], b0, b1);
                }
            }
            __syncthreads();
        }
#pragma unroll
        for (int mt = 0; mt < 2; mt++) {
#pragma unroll
            for (int h = 0; h < 2; h++) {
                int r = bm + wm * 32 + mt * 16 + g + h * 8;
#pragma unroll
                for (int nt = 0; nt < 8; nt++) {
                    int c = wn * 64 + nt * 8 + 2 * t;
                    float2 bbv = *(const float2*)(bb + nc * 128 + c);
                    float2 o;
                    o.x = acc[mt][nt][2 * h + 0] + bbv.x;
                    o.y = acc[mt][nt][2 * h + 1] + bbv.y;
                    *(float2*)(C + (size_t)r * 384 + nc * 128 + c) = o;
                }
            }
        }
    }
}

// ---------------------------------------------------------------------------
// vproj GEMM: g_vproj[3N,256] = rna(g_dvec)[3N,128] @ Wvt[128,256].
// One block stages A once and computes both 128-col halves.
// ---------------------------------------------------------------------------
__global__ void __launch_bounds__(256, 2)
gemm_vproj(float* __restrict__ C) {
    extern __shared__ float sm[];
    float* As = sm;                 // 128 x 132
    float* Bs = sm + 128 * 132;     // 2 x 32 x 136
    int tid = threadIdx.x;
    int bm = blockIdx.x * 128;

    // stage full A (K=128) with rna in flight
#pragma unroll
    for (int i = 0; i < 16; i++) {
        int f = tid + i * 256;
        int row = f >> 5, c4 = (f & 31) * 4;
        float4 v = rnd4(*(const float4*)(g_dvec + (size_t)(bm + row) * 128 + c4));
        *(float4*)(As + row * 132 + c4) = v;
    }

    int wid = tid >> 5, lane = tid & 31;
    int g = lane >> 2, t = lane & 3;
    int wm = wid >> 1, wn = wid & 1;
    int mbase = wm * 32;
    float acc[2][8][4];

#pragma unroll 1
    for (int nc = 0; nc < 2; nc++) {
        const float* B = g_Wvt + nc * 128;   // ldb = 256
        ACC_INIT(acc)
#pragma unroll
        for (int i = 0; i < 4; i++) {
            int f = tid + i * 256;
            int row = f >> 5, c4 = (f & 31) * 4;
            cp16(Bs + row * 136 + c4, B + (size_t)row * 256 + c4);
        }
        asm volatile("cp.async.commit_group;" ::: "memory");
        for (int kc = 0; kc < 4; kc++) {
            if (kc < 3) {
                int k0 = (kc + 1) * 32;
                float* bs = Bs + ((kc + 1) & 1) * (32 * 136);
#pragma unroll
                for (int i = 0; i < 4; i++) {
                    int f = tid + i * 256;
                    int row = f >> 5, c4 = (f & 31) * 4;
                    cp16(bs + row * 136 + c4, B + (size_t)(k0 + row) * 256 + c4);
                }
                asm volatile("cp.async.commit_group;" ::: "memory");
                asm volatile("cp.async.wait_group 1;" ::: "memory");
            } else {
                asm volatile("cp.async.wait_group 0;" ::: "memory");
            }
            __syncthreads();
            const float* bs = Bs + (kc & 1) * (32 * 136);
            int kg = kc * 32;
#pragma unroll
            for (int ks = 0; ks < 4; ks++) {
                int kk = kg + ks * 8;
                uint32_t af[2][4];
#pragma unroll
                for (int mt = 0; mt < 2; mt++) {
                    int r0 = mbase + mt * 16;
                    af[mt][0] = __float_as_uint(As[(r0 + g) * 132 + kk + t]);
                    af[mt][1] = __float_as_uint(As[(r0 + g + 8) * 132 + kk + t]);
                    af[mt][2] = __float_as_uint(As[(r0 + g) * 132 + kk + t + 4]);
                    af[mt][3] = __float_as_uint(As[(r0 + g + 8) * 132 + kk + t + 4]);
                }
#pragma unroll
                for (int nt = 0; nt < 8; nt++) {
                    int cb = wn * 64 + nt * 8;
                    uint32_t b0 = __float_as_uint(bs[(ks * 8 + t) * 136 + cb + g]);
                    uint32_t b1 = __float_as_uint(bs[(ks * 8 + t + 4) * 136 + cb + g]);
#pragma unroll
                    for (int mt = 0; mt < 2; mt++) mma8(acc[mt][nt], af[mt], b0, b1);
                }
            }
            __syncthreads();
        }
#pragma unroll
        for (int mt = 0; mt < 2; mt++) {
#pragma unroll
            for (int h = 0; h < 2; h++) {
                int r = bm + wm * 32 + mt * 16 + g + h * 8;
#pragma unroll
                for (int nt = 0; nt < 8; nt++) {
                    int c = wn * 64 + nt * 8 + 2 * t;
                    float2 o = {acc[mt][nt][2 * h + 0], acc[mt][nt][2 * h + 1]};
                    *(float2*)(C + (size_t)r * 256 + nc * 128 + c) = o;
                }
            }
        }
    }
}

// ---------------------------------------------------------------------------
// Merged edge kernel (segregated): blocks [0,4096) dx; [4096,12288) dvec.
// ---------------------------------------------------------------------------
__global__ void __launch_bounds__(256, 2)
edge_gemm_all(const float* __restrict__ ee, const float* __restrict__ br,
              const int* __restrict__ ei, const float* __restrict__ vec,
              const float* __restrict__ evec) {
    const int ESW = 68;
    extern __shared__ float sm[];
    __shared__ int s_src[128];
    __shared__ int s_dst[128];
    __shared__ float s_ev[3][64];
    int tid = threadIdx.x;

    if (blockIdx.x < 4096) {
        const int BSW = 136;
        float* As = sm;
        float* Bs = sm + 128 * ESW;
        int bm = blockIdx.x * 128;

#pragma unroll
        for (int i = 0; i < 8; i++) {
            int f = tid + i * 256;
            int row = f >> 5, c4 = (f & 31) * 4;
            cp16(Bs + row * BSW + c4, g_Wrt + (size_t)row * 384 + c4);
        }
        asm volatile("cp.async.commit_group;" ::: "memory");

        if (tid < 128) {
            s_src[tid] = __ldcs(ei + bm + tid);
            s_dst[tid] = __ldcs(ei + NE + bm + tid);
        }

#pragma unroll
        for (int i = 0; i < 8; i++) {
            int f = tid + i * 256;
            int row = f >> 4, c4 = (f & 15) * 4;
            float4 v = rnd4(ld_cs4(ee + (size_t)(bm + row) * 64 + c4));
            *(float4*)(As + row * ESW + c4) = v;
        }
        asm volatile("cp.async.wait_group 0;" ::: "memory");
        __syncthreads();

        float acc[2][8][4];
        ACC_INIT(acc)
        edge_mma_compute<128, 128>(As, Bs, acc);
        __syncthreads();

        float* sbuf = sm;   // 128 x 132
        int wid = tid >> 5, lane = tid & 31;
        int g = lane >> 2, t = lane & 3;
        int wm = wid >> 1, wn = wid & 1;
#pragma unroll
        for (int mt = 0; mt < 2; mt++) {
#pragma unroll
            for (int h = 0; h < 2; h++) {
                int row = wm * 32 + mt * 16 + g + h * 8;
#pragma unroll
                for (int nt = 0; nt < 8; nt++) {
                    int col = wn * 64 + nt * 8 + 2 * t;
                    float2 bb = *(const float2*)(br + col);
                    sbuf[row * 132 + col]     = acc[mt][nt][2 * h + 0] + bb.x;
                    sbuf[row * 132 + col + 1] = acc[mt][nt][2 * h + 1] + bb.y;
                }
            }
        }
        __syncthreads();
#pragma unroll
        for (int i = 0; i < 16; i++) {
            int f = tid + i * 256;
            int e = f >> 5;
            int c4 = (f & 31) * 4;
            int src = s_src[e], dst = s_dst[e];
            float4 m = *(float4*)(sbuf + e * 132 + c4);
            float4 x1 = *(const float4*)(g_xh + (size_t)src * 384 + c4);
            m.x *= x1.x; m.y *= x1.y; m.z *= x1.z; m.w *= x1.w;
            red4(g_dx + (size_t)dst * HD + c4, m);
        }
    } else {
        const int BSW = 264;
        float* As = sm;
        float* Bs = sm + 64 * ESW;
        int bm = (blockIdx.x - 4096) * 64;

#pragma unroll
        for (int i = 0; i < 16; i++) {
            int f = tid + i * 256;
            int row = f >> 6, c4 = (f & 63) * 4;
            cp16(Bs + row * BSW + c4, g_Wrt + 128 + (size_t)row * 384 + c4);
        }
        asm volatile("cp.async.commit_group;" ::: "memory");

        if (tid < 64) {
            s_src[tid] = __ldcs(ei + bm + tid);
            s_dst[tid] = __ldcs(ei + NE + bm + tid);
        }
        if (tid < 192) {
            int e = tid & 63;
            int c = tid >> 6;
            s_ev[c][e] = __ldcs(evec + (size_t)(bm + e) * 3 + c);
        }

#pragma unroll
        for (int i = 0; i < 4; i++) {
            int f = tid + i * 256;
            int row = f >> 4, c4 = (f & 15) * 4;
            float4 v = rnd4(ld_cs4(ee + (size_t)(bm + row) * 64 + c4));
            *(float4*)(As + row * ESW + c4) = v;
        }
        asm volatile("cp.async.wait_group 0;" ::: "memory");
        __syncthreads();

        float acc[2][8][4];
        ACC_INIT(acc)
        edge_mma_compute<64, 256>(As, Bs, acc);
        __syncthreads();

        float* sbuf = sm;   // 64 x 260
        int wid = tid >> 5, lane = tid & 31;
        int g = lane >> 2, t = lane & 3;
        int wm = wid >> 2, wn = wid & 3;
#pragma unroll
        for (int mt = 0; mt < 2; mt++) {
#pragma unroll
            for (int h = 0; h < 2; h++) {
                int row = wm * 32 + mt * 16 + g + h * 8;
#pragma unroll
                for (int nt = 0; nt < 8; nt++) {
                    int col = wn * 64 + nt * 8 + 2 * t;
                    float2 bb = *(const float2*)(br + 128 + col);
                    sbuf[row * 260 + col]     = acc[mt][nt][2 * h + 0] + bb.x;
                    sbuf[row * 260 + col + 1] = acc[mt][nt][2 * h + 1] + bb.y;
                }
            }
        }
        __syncthreads();
#pragma unroll
        for (int i = 0; i < 8; i++) {
            int f = tid + i * 256;
            int e = f >> 5;
            int c4 = (f & 31) * 4;
            int src = s_src[e], dst = s_dst[e];
            float ev0 = s_ev[0][e], ev1 = s_ev[1][e], ev2 = s_ev[2][e];
            float4 r2 = *(float4*)(sbuf + e * 260 + c4);
            float4 r3 = *(float4*)(sbuf + e * 260 + 128 + c4);
            const float* xhp = g_xh + (size_t)src * 384;
            float4 x2 = *(const float4*)(xhp + 128 + c4);
            float4 x3 = *(const float4*)(xhp + 256 + c4);
            float4 m2, m3;
            m2.x = r2.x * x2.x * C_INV_SQRT_3; m2.y = r2.y * x2.y * C_INV_SQRT_3;
            m2.z = r2.z * x2.z * C_INV_SQRT_3; m2.w = r2.w * x2.w * C_INV_SQRT_3;
            m3.x = r3.x * x3.x; m3.y = r3.y * x3.y;
            m3.z = r3.z * x3.z; m3.w = r3.w * x3.w;
            const float* vp = vec + (size_t)src * 384;
            float* dvp = g_dvec + (size_t)dst * 384;
#pragma unroll
            for (int c = 0; c < 3; c++) {
                float ev = (c == 0) ? ev0 : ((c == 1) ? ev1 : ev2);
                float4 vv = *(const float4*)(vp + c * 128 + c4);
                float4 msg;
                msg.x = (vv.x * m2.x + m3.x * ev) * C_INV_SQRT_H;
                msg.y = (vv.y * m2.y + m3.y * ev) * C_INV_SQRT_H;
                msg.z = (vv.z * m2.z + m3.z * ev) * C_INV_SQRT_H;
                msg.w = (vv.w * m2.w + m3.w * ev) * C_INV_SQRT_H;
                red4(dvp + c * 128 + c4, msg);
            }
        }
    }
}

// ---------------------------------------------------------------------------
__global__ void dotnorm_kernel() {
    int i = blockIdx.x * blockDim.x + threadIdx.x;
    if (i >= NN * HD) return;
    int n = i >> 7;
    int h = i & 127;
    const float* vp = g_vproj + (size_t)n * 768;
    float d = 0.f, s = 0.f;
#pragma unroll
    for (int c = 0; c < 3; c++) {
        float v1 = vp[c * 256 + h];
        float v2 = vp[c * 256 + 128 + h];
        d += v1 * v2;
        s += v2 * v2;
    }
    float xn = g_dx[i] * C_INV_SQRT_2;
    g_vecdot[i] = d * C_INV_SQRT_H;
    g_cat[(size_t)n * 256 + h] = f2tf32(xn);
    g_cat[(size_t)n * 256 + 128 + h] = f2tf32(sqrtf(s + 1e-8f));
}

// ---------------------------------------------------------------------------
__global__ void finalize_kernel(float* __restrict__ out) {
    int i = blockIdx.x * blockDim.x + threadIdx.x;
    if (i >= NN * HD) return;
    int n = i >> 7;
    int h = i & 127;
    const float* hb = g_hbuf + (size_t)n * 384;
    float xv1 = hb[h];
    float xv2 = hb[128 + h];
    float xv3 = hb[256 + h];
    float* out_vec = out;
    float* out_x = out + (size_t)NN * 3 * HD;
    float xn = g_dx[i] * C_INV_SQRT_2;
    out_x[i] = xn + (xv1 + xv2 * g_vecdot[i]) * C_INV_SQRT_2;
#pragma unroll
    for (int c = 0; c < 3; c++) {
        size_t idx = (size_t)n * 384 + c * HD + h;
        out_vec[idx] = g_dvec[idx] + xv3 * g_vproj[(size_t)n * 768 + c * 256 + h];
    }
}

// ---------------------------------------------------------------------------
extern "C" void kernel_launch(void* const* d_in, const int* in_sizes, int n_in,
                              void* d_out, int out_size) {
    const float* x    = (const float*)d_in[0];
    const float* vec  = (const float*)d_in[1];
    const int*   ei   = (const int*)d_in[2];
    const float* ee   = (const float*)d_in[3];
    const float* evec = (const float*)d_in[4];
    const float* ln_g = (const float*)d_in[5];
    const float* ln_b = (const float*)d_in[6];
    const float* W1   = (const float*)d_in[7];
    const float* b1   = (const float*)d_in[8];
    const float* W2   = (const float*)d_in[9];
    const float* b2   = (const float*)d_in[10];
    const float* Wr   = (const float*)d_in[11];
    const float* br   = (const float*)d_in[12];
    const float* Wv   = (const float*)d_in[13];
    const float* Wu1  = (const float*)d_in[14];
    const float* bu1  = (const float*)d_in[15];
    const float* Wu2  = (const float*)d_in[16];
    const float* bu2  = (const float*)d_in[17];

    float* out = (float*)d_out;

    float* xln = nullptr;     cudaGetSymbolAddress((void**)&xln, g_xln);
    float* vproj = nullptr;   cudaGetSymbolAddress((void**)&vproj, g_vproj);
    float* cat = nullptr;     cudaGetSymbolAddress((void**)&cat, g_cat);
    float* hbuf = nullptr;    cudaGetSymbolAddress((void**)&hbuf, g_hbuf);
    float* xh = nullptr;      cudaGetSymbolAddress((void**)&xh, g_xh);
    float* w1t = nullptr;     cudaGetSymbolAddress((void**)&w1t, g_W1t);
    float* w2t = nullptr;     cudaGetSymbolAddress((void**)&w2t, g_W2t);
    float* wu1t = nullptr;    cudaGetSymbolAddress((void**)&wu1t, g_Wu1t);
    float* wu2t = nullptr;    cudaGetSymbolAddress((void**)&wu2t, g_Wu2t);

    const int SMEM_EDGE  = (64 * 68 + 64 * 264) * 4;            // 84992
    const int SMEM_VPROJ = (128 * 132 + 2 * 32 * 136) * 4;      // 102400
    const int SMEM_FMLP  = (2 * 128 * ASW + 2 * 32 * 136 + 2 * 32 * 136) * 4; // 106496

    cudaFuncSetAttribute((const void*)fused_mlp<128>,
                         cudaFuncAttributeMaxDynamicSharedMemorySize, SMEM_FMLP);
    cudaFuncSetAttribute((const void*)fused_mlp<256>,
                         cudaFuncAttributeMaxDynamicSharedMemorySize, SMEM_FMLP);
    cudaFuncSetAttribute((const void*)edge_gemm_all,
                         cudaFuncAttributeMaxDynamicSharedMemorySize, SMEM_EDGE);
    cudaFuncSetAttribute((const void*)gemm_vproj,
                         cudaFuncAttributeMaxDynamicSharedMemorySize, SMEM_VPROJ);

    // 1. prep: LN + g_dx=x + dvec=vec + weight rounding
    prep_kernel<<<4096 + 4096, 256>>>(x, vec, ln_g, ln_b,
                                      W1, W2, Wr, Wv, Wu1, Wu2);

    // 2. fused message MLP: xh = (ssilu(xln@W1+b1)) @ W2 + b2
    fused_mlp<128><<<NN / 128, 256, SMEM_FMLP>>>(xln, w1t, b1, w2t, b2, xh);

    // 3. merged edge kernel
    edge_gemm_all<<<4096 + 8192, 256, SMEM_EDGE>>>(ee, br, ei, vec, evec);

    // 4. vproj = rna(vec_new) @ Wv (both col halves per block, A staged once)
    gemm_vproj<<<(3 * NN) / 128, 256, SMEM_VPROJ>>>(vproj);

    // 5. x_new + vec_dot / vec2_norm / cat
    dotnorm_kernel<<<(NN * HD) / 256, 256>>>();

    // 6. fused update MLP: hbuf = (ssilu(cat@Wu1+bu1)) @ Wu2 + bu2
    fused_mlp<256><<<NN / 128, 256, SMEM_FMLP>>>(cat, wu1t, bu1, wu2t, bu2, hbuf);

    // 7. finalize
    finalize_kernel<<<(NN * HD) / 256, 256>>>(out);
}